// round 13
// baseline (speedup 1.0000x reference)
#include <cuda_runtime.h>
#include <math.h>
#include <stdint.h>

// ---------------- problem constants ----------------
#define NN      20000      // nodes
#define FEAT    128
#define E0      100000     // undirected edges
#define EDG     200000     // directed (doubled)
#define NRBF    20
#define NCONV   3
#define CUTOFF  20.0f
#define PI_F    3.14159265358979323846f

#define NF      (NN*FEAT)          // 2,560,000
#define N3F     (NN*384)           // 7,680,000

// hybrid split: tensor warps cover cols [0,72), scalar warps [72,128)
#define TCOLS 72
#define SCOLS 56

// ---------------- device scratch (no cudaMalloc allowed) ----------------
__device__ float g_s [NF];
__device__ float g_vA[3*NF];
__device__ float g_vB[3*NF];
__device__ float g_phi[N3F];
__device__ float g_hid[NF];
__device__ float g_uv[3*NF];
__device__ float g_vv[3*NF];
__device__ float g_am[N3F];
__device__ float g_unit[EDG*3];
__device__ float g_rbf[EDG*NRBF];
__device__ float g_env[EDG];
__device__ int   g_ei[EDG];
__device__ int   g_ej[EDG];
// CSR sort scratch
__device__ int   g_deg[NN];
__device__ int   g_pos[NN];
__device__ int   g_start[NN+1];
__device__ int   g_sorted[EDG];

// ---------------- helpers ----------------
__device__ __forceinline__ float tf32_rna(float x) {
    uint32_t u; asm("cvt.rna.tf32.f32 %0, %1;" : "=r"(u) : "f"(x));
    return __uint_as_float(u);
}
__device__ __forceinline__ void mma_tf32(float* c, const uint32_t* a, uint32_t b0, uint32_t b1) {
    asm volatile(
        "mma.sync.aligned.m16n8k8.row.col.f32.tf32.tf32.f32 "
        "{%0,%1,%2,%3}, {%4,%5,%6,%7}, {%8,%9}, {%0,%1,%2,%3};"
        : "+f"(c[0]), "+f"(c[1]), "+f"(c[2]), "+f"(c[3])
        : "r"(a[0]), "r"(a[1]), "r"(a[2]), "r"(a[3]), "r"(b0), "r"(b1));
}
__device__ __forceinline__ void cp16(uint32_t dst, const void* src, bool pred) {
    int sz = pred ? 16 : 0;
    asm volatile("cp.async.ca.shared.global [%0], [%1], 16, %2;"
                 :: "r"(dst), "l"(src), "r"(sz) : "memory");
}

// ---------------- small utility kernels ----------------
__global__ void copy4_kernel(float4* __restrict__ dst, const float4* __restrict__ src, int n4) {
    int i = blockIdx.x * blockDim.x + threadIdx.x;
    if (i < n4) dst[i] = src[i];
}
__global__ void zero4_kernel(float4* __restrict__ dst, int n4) {
    int i = blockIdx.x * blockDim.x + threadIdx.x;
    if (i < n4) dst[i] = make_float4(0.f,0.f,0.f,0.f);
}
__global__ void zeroi_kernel(int* __restrict__ a, int* __restrict__ b, int n) {
    int i = blockIdx.x * blockDim.x + threadIdx.x;
    if (i < n) { a[i] = 0; b[i] = 0; }
}

// ---------------- edge geometry precompute ----------------
__global__ void edge_geom_kernel(const float* __restrict__ xyz, const int* __restrict__ nbr,
                                 float* __restrict__ unit, float* __restrict__ rbf,
                                 float* __restrict__ env, int* __restrict__ ei, int* __restrict__ ej) {
    int e = blockIdx.x * blockDim.x + threadIdx.x;
    if (e >= EDG) return;
    int p = (e < E0) ? e : (e - E0);
    int a = nbr[p*2], b = nbr[p*2+1];
    int i = (e < E0) ? a : b;
    int j = (e < E0) ? b : a;
    float dx = xyz[j*3+0] - xyz[i*3+0];
    float dy = xyz[j*3+1] - xyz[i*3+1];
    float dz = xyz[j*3+2] - xyz[i*3+2];
    float d  = sqrtf(dx*dx + dy*dy + dz*dz);
    float invd = 1.0f / d;
    unit[e*3+0] = dx*invd; unit[e*3+1] = dy*invd; unit[e*3+2] = dz*invd;
    #pragma unroll
    for (int k = 0; k < NRBF; k++)
        rbf[e*NRBF + k] = sinf((float)(k+1) * PI_F * d / CUTOFF) * invd;
    env[e] = (d < CUTOFF) ? 0.5f * (cosf(PI_F * d / CUTOFF) + 1.0f) : 0.0f;
    ei[e] = i; ej[e] = j;
}

// ---------------- CSR build: histogram, scan, scatter ----------------
__global__ void hist_kernel(const int* __restrict__ ei, int* __restrict__ deg) {
    int e = blockIdx.x * blockDim.x + threadIdx.x;
    if (e < EDG) atomicAdd(&deg[ei[e]], 1);
}
__global__ void scan_kernel(const int* __restrict__ deg, int* __restrict__ start) {
    __shared__ int ssum[1024];
    const int tid = threadIdx.x;
    const int CH = (NN + 1023) / 1024;   // 20
    int base = tid * CH;
    int local = 0;
    for (int k = 0; k < CH; k++) {
        int idx = base + k;
        if (idx < NN) local += deg[idx];
    }
    ssum[tid] = local;
    __syncthreads();
    for (int off = 1; off < 1024; off <<= 1) {
        int t = (tid >= off) ? ssum[tid - off] : 0;
        __syncthreads();
        ssum[tid] += t;
        __syncthreads();
    }
    int run = ssum[tid] - local;
    for (int k = 0; k < CH; k++) {
        int idx = base + k;
        if (idx < NN) { start[idx] = run; run += deg[idx]; }
    }
    if (tid == 1023) start[NN] = ssum[1023];
}
__global__ void scatter_kernel(const int* __restrict__ ei, const int* __restrict__ start,
                               int* __restrict__ pos, int* __restrict__ sorted) {
    int e = blockIdx.x * blockDim.x + threadIdx.x;
    if (e >= EDG) return;
    int i = ei[e];
    int p = start[i] + atomicAdd(&pos[i], 1);
    sorted[p] = e;
}

// =====================================================================
// HYBRID GEMM: C = act(A @ W^T + b).
// Per 128x128 tile, 8 warps: warps 0-3 (tensor role) compute cols [0,72)
// with tf32x3 mma.sync; warps 4-7 (scalar role, paired on the same SMSPs)
// compute cols [72,128) with exact fp32 FFMA — tensor and fma pipes run
// concurrently. Staging (cp.async, double-buffered) unchanged from R6.
// XCAT: A is the implicit [s | norm(vv)] matrix (K=256).
// =====================================================================
#define PITCH 20
template<bool SILU, bool XCAT>
__global__ void __launch_bounds__(256)
mma_gemm_kernel(const float* __restrict__ A, size_t aStride,
                const float* __restrict__ W, const float* __restrict__ W2,
                const float* __restrict__ bias,
                float* __restrict__ C, float* __restrict__ C2, size_t cStride,
                const float* __restrict__ vvSrc,
                int Nrows, int Mcols, int K) {
    __shared__ float As[2][128 * PITCH];
    __shared__ float Bs[2][128 * PITCH];

    const int tid = threadIdx.x;
    const int wid = tid >> 5;
    const int lid = tid & 31;
    const int tq  = lid >> 2;
    const int tr  = lid & 3;
    const bool tensorRole = (wid < 4);
    const int warpRow = (wid & 3) * 32;
    const int rowBase = blockIdx.y * 128;

    const int colTiles = (Mcols + 127) >> 7;
    int bx = blockIdx.x;
    const float* Wsel = W;
    float* Csel = C;
    if (W2 != nullptr && bx >= colTiles) { Wsel = W2; Csel = C2; bx -= colTiles; }
    const int colBase = bx * 128;

    A    += (size_t)blockIdx.z * aStride;
    Csel += (size_t)blockIdx.z * cStride;
    const float* Wt = Wsel + (size_t)colBase * K;

    const uint32_t aSm0 = (uint32_t)__cvta_generic_to_shared(&As[0][0]);
    const uint32_t aSm1 = (uint32_t)__cvta_generic_to_shared(&As[1][0]);
    const uint32_t bSm0 = (uint32_t)__cvta_generic_to_shared(&Bs[0][0]);
    const uint32_t bSm1 = (uint32_t)__cvta_generic_to_shared(&Bs[1][0]);

    const int ldRow0 = tid >> 2;
    const int ldQ    = (tid & 3) * 4;

    // accumulators: tensor role uses [2][9][4] = 72 floats; scalar role uses 56.
    float acc[TCOLS];
    #pragma unroll
    for (int u = 0; u < TCOLS; u++) acc[u] = 0.f;

    const int nch = K >> 4;

    auto issue_stage = [&](int c, int buf) {
        const int k0 = c * 16;
        uint32_t aSm = buf ? aSm1 : aSm0;
        uint32_t bSm = buf ? bSm1 : bSm0;
        #pragma unroll
        for (int half = 0; half < 2; half++) {
            int row = half * 64 + ldRow0;
            int r = rowBase + row;
            uint32_t soff = (uint32_t)(row * PITCH + ldQ) * 4u;
            if (!XCAT) {
                cp16(aSm + soff, &A[(size_t)r * K + k0 + ldQ], r < Nrows);
            } else {
                if (k0 < 128) {
                    cp16(aSm + soff, &A[(size_t)r * 128 + k0 + ldQ], r < Nrows);
                } else {
                    float4 o = make_float4(0.f,0.f,0.f,0.f);
                    if (r < Nrows) {
                        size_t base = (size_t)r * 128 + (k0 - 128) + ldQ;
                        #pragma unroll
                        for (int q = 0; q < 4; q++) {
                            float a = vvSrc[base + q];
                            float b = vvSrc[NF + base + q];
                            float cc = vvSrc[2*NF + base + q];
                            float n = sqrtf(a*a + b*b + cc*cc);
                            if (q == 0) o.x = n; else if (q == 1) o.y = n;
                            else if (q == 2) o.z = n; else o.w = n;
                        }
                    }
                    float* dst = (buf ? As[1] : As[0]) + row * PITCH + ldQ;
                    *(float4*)dst = o;
                }
            }
            cp16(bSm + soff, &Wt[(size_t)row * K + k0 + ldQ], true);
        }
        asm volatile("cp.async.commit_group;" ::: "memory");
    };

    issue_stage(0, 0);

    for (int c = 0; c < nch; c++) {
        if (c + 1 < nch) {
            issue_stage(c + 1, (c + 1) & 1);
            asm volatile("cp.async.wait_group 1;" ::: "memory");
        } else {
            asm volatile("cp.async.wait_group 0;" ::: "memory");
        }
        __syncthreads();

        const float* Ab = As[c & 1];
        const float* Bb = Bs[c & 1];

        if (tensorRole) {
            // ---- tensor path: cols [0, 72), 9 n-frags ----
            #pragma unroll
            for (int ks = 0; ks < 2; ks++) {
                const int kc = ks * 8;
                uint32_t ah[2][4], al[2][4];
                #pragma unroll
                for (int mf = 0; mf < 2; mf++) {
                    int r0 = warpRow + mf * 16 + tq;
                    float a0 = Ab[(r0    ) * PITCH + kc + tr    ];
                    float a1 = Ab[(r0 + 8) * PITCH + kc + tr    ];
                    float a2 = Ab[(r0    ) * PITCH + kc + tr + 4];
                    float a3 = Ab[(r0 + 8) * PITCH + kc + tr + 4];
                    float h0 = tf32_rna(a0), h1 = tf32_rna(a1), h2 = tf32_rna(a2), h3 = tf32_rna(a3);
                    ah[mf][0] = __float_as_uint(h0); al[mf][0] = __float_as_uint(a0 - h0);
                    ah[mf][1] = __float_as_uint(h1); al[mf][1] = __float_as_uint(a1 - h1);
                    ah[mf][2] = __float_as_uint(h2); al[mf][2] = __float_as_uint(a2 - h2);
                    ah[mf][3] = __float_as_uint(h3); al[mf][3] = __float_as_uint(a3 - h3);
                }
                #pragma unroll
                for (int nf = 0; nf < 9; nf++) {
                    int c0 = nf * 8 + tq;
                    float b0 = Bb[c0 * PITCH + kc + tr    ];
                    float b1 = Bb[c0 * PITCH + kc + tr + 4];
                    float bh0f = tf32_rna(b0), bh1f = tf32_rna(b1);
                    uint32_t bh0 = __float_as_uint(bh0f);
                    uint32_t bh1 = __float_as_uint(bh1f);
                    uint32_t bl0 = __float_as_uint(b0 - bh0f);
                    uint32_t bl1 = __float_as_uint(b1 - bh1f);
                    #pragma unroll
                    for (int mf = 0; mf < 2; mf++) {
                        float* a4 = &acc[(mf * 9 + nf) * 4];
                        mma_tf32(a4, ah[mf], bh0, bh1);
                        mma_tf32(a4, al[mf], bh0, bh1);
                        mma_tf32(a4, ah[mf], bl0, bl1);
                    }
                }
            }
        } else {
            // ---- scalar path: cols [72, 128); lane -> 1 row, 56 cols ----
            const float* Arow = &Ab[(warpRow + lid) * PITCH];
            #pragma unroll 1
            for (int k4 = 0; k4 < 4; k4++) {
                float4 a4 = *(const float4*)&Arow[k4 * 4];
                #pragma unroll
                for (int cc = 0; cc < SCOLS; cc++) {
                    float4 b4 = *(const float4*)&Bb[(TCOLS + cc) * PITCH + k4 * 4];
                    acc[cc] = fmaf(a4.x, b4.x,
                               fmaf(a4.y, b4.y,
                                fmaf(a4.z, b4.z,
                                 fmaf(a4.w, b4.w, acc[cc]))));
                }
            }
        }
        __syncthreads();
    }

    // ---------------- epilogues ----------------
    if (tensorRole) {
        #pragma unroll
        for (int mf = 0; mf < 2; mf++) {
            int r0 = rowBase + warpRow + mf * 16 + tq;
            #pragma unroll
            for (int nf = 0; nf < 9; nf++) {
                int cb = colBase + nf * 8 + tr * 2;
                float b0 = bias ? bias[cb] : 0.f;
                float b1 = bias ? bias[cb + 1] : 0.f;
                const float* a4 = &acc[(mf * 9 + nf) * 4];
                float v0 = a4[0] + b0;
                float v1 = a4[1] + b1;
                float v2 = a4[2] + b0;
                float v3 = a4[3] + b1;
                if (SILU) {
                    v0 = v0 / (1.f + expf(-v0));
                    v1 = v1 / (1.f + expf(-v1));
                    v2 = v2 / (1.f + expf(-v2));
                    v3 = v3 / (1.f + expf(-v3));
                }
                if (r0 < Nrows)      *(float2*)&Csel[(size_t)r0      * Mcols + cb] = make_float2(v0, v1);
                if (r0 + 8 < Nrows)  *(float2*)&Csel[(size_t)(r0 + 8) * Mcols + cb] = make_float2(v2, v3);
            }
        }
    } else {
        int r = rowBase + warpRow + lid;
        if (r < Nrows) {
            #pragma unroll
            for (int cc = 0; cc < SCOLS; cc += 4) {
                int cb = colBase + TCOLS + cc;
                float4 bv = bias ? *(const float4*)&bias[cb] : make_float4(0.f,0.f,0.f,0.f);
                float4 o;
                o.x = acc[cc]     + bv.x;
                o.y = acc[cc + 1] + bv.y;
                o.z = acc[cc + 2] + bv.z;
                o.w = acc[cc + 3] + bv.w;
                if (SILU) {
                    o.x = o.x / (1.f + expf(-o.x));
                    o.y = o.y / (1.f + expf(-o.y));
                    o.z = o.z / (1.f + expf(-o.z));
                    o.w = o.w / (1.f + expf(-o.w));
                }
                *(float4*)&Csel[(size_t)r * Mcols + cb] = o;
            }
        }
    }
}

// ---------------- per-node edge gather (R10 winner) ----------------
__global__ void __launch_bounds__(128)
edge_node_kernel(const float* __restrict__ phi,
                 const float* __restrict__ v_old,
                 const float* __restrict__ distW,
                 const float* __restrict__ distb,
                 const int* __restrict__ ej,
                 const float* __restrict__ unit, const float* __restrict__ rbf,
                 const float* __restrict__ env,
                 const int* __restrict__ start, const int* __restrict__ sorted,
                 float* __restrict__ s, float* __restrict__ v_new) {
    const int n = blockIdx.x;
    const int f = threadIdx.x;

    float w[3][NRBF];
    float bch[3];
    #pragma unroll
    for (int c = 0; c < 3; c++) {
        const float4* src = (const float4*)&distW[(c * 128 + f) * NRBF];
        #pragma unroll
        for (int q = 0; q < 5; q++) {
            float4 v4 = src[q];
            w[c][q*4+0] = v4.x; w[c][q*4+1] = v4.y; w[c][q*4+2] = v4.z; w[c][q*4+3] = v4.w;
        }
        bch[c] = distb[c * 128 + f];
    }

    const size_t nb = (size_t)n * 128 + f;
    float sAcc = s[nb];
    float a0 = v_old[nb];
    float a1 = v_old[NF + nb];
    float a2 = v_old[2*NF + nb];

    const int e0 = start[n], e1 = start[n + 1];
    for (int k = e0; k < e1; k++) {
        int e = sorted[k];
        int j = ej[e];
        float rb[NRBF];
        {
            const float4* src = (const float4*)&rbf[e * NRBF];
            #pragma unroll
            for (int q = 0; q < 5; q++) {
                float4 v4 = src[q];
                rb[q*4+0] = v4.x; rb[q*4+1] = v4.y; rb[q*4+2] = v4.z; rb[q*4+3] = v4.w;
            }
        }
        float ev = env[e];
        float u0 = unit[e*3+0], u1 = unit[e*3+1], u2 = unit[e*3+2];

        const float* phij = phi + (size_t)j * 384 + f;
        float inv[3];
        #pragma unroll
        for (int c = 0; c < 3; c++) {
            float acc2 = bch[c];
            #pragma unroll
            for (int kk = 0; kk < NRBF; kk++) acc2 += rb[kk] * w[c][kk];
            inv[c] = phij[c * 128] * (acc2 * ev);
        }

        const size_t jb = (size_t)j * 128 + f;
        sAcc += inv[1];
        a0 += inv[2]*u0 + inv[0]*v_old[jb];
        a1 += inv[2]*u1 + inv[0]*v_old[NF + jb];
        a2 += inv[2]*u2 + inv[0]*v_old[2*NF + jb];
    }

    s[nb] = sAcc;
    v_new[nb]        = a0;
    v_new[NF + nb]   = a1;
    v_new[2*NF + nb] = a2;
}

// ---------------- final gated update (optionally fused output pack) ----------------
__global__ void update_kernel(const float* __restrict__ uv, const float* __restrict__ vv,
                              const float* __restrict__ am,
                              float* __restrict__ s, float* __restrict__ v,
                              float* __restrict__ out) {
    int idx = blockIdx.x * blockDim.x + threadIdx.x;
    if (idx >= NF) return;
    int n = idx >> 7, f = idx & 127;
    float dot = uv[idx]*vv[idx] + uv[NF+idx]*vv[NF+idx] + uv[2*NF+idx]*vv[2*NF+idx];
    float a0 = am[(size_t)n*384 + f];
    float a1 = am[(size_t)n*384 + 128 + f];
    float a2 = am[(size_t)n*384 + 256 + f];
    float sNew = s[idx] + dot * a1 + a2;
    s[idx] = sNew;
    float vNew[3];
    #pragma unroll
    for (int d = 0; d < 3; d++) {
        vNew[d] = v[(size_t)d*NF + idx] + uv[(size_t)d*NF + idx] * a0;
        v[(size_t)d*NF + idx] = vNew[d];
    }
    if (out != nullptr) {
        out[idx] = sNew;
        #pragma unroll
        for (int d = 0; d < 3; d++)
            out[(size_t)NF + (size_t)n*384 + f*3 + d] = vNew[d];
    }
}

// ---------------- host orchestration ----------------
extern "C" void kernel_launch(void* const* d_in, const int* in_sizes, int n_in,
                              void* d_out, int out_size) {
    const float* xyz    = (const float*)d_in[0];
    const int*   nbr    = (const int*)  d_in[1];
    const float* cg_s   = (const float*)d_in[2];
    const float* msg_W1 = (const float*)d_in[3];
    const float* msg_b1 = (const float*)d_in[4];
    const float* msg_W2 = (const float*)d_in[5];
    const float* msg_b2 = (const float*)d_in[6];
    const float* dist_W = (const float*)d_in[7];
    const float* dist_b = (const float*)d_in[8];
    const float* upd_U  = (const float*)d_in[9];
    const float* upd_V  = (const float*)d_in[10];
    const float* upd_sW1= (const float*)d_in[11];
    const float* upd_sb1= (const float*)d_in[12];
    const float* upd_sW2= (const float*)d_in[13];
    const float* upd_sb2= (const float*)d_in[14];
    float* out = (float*)d_out;

    float *s, *vA, *vB, *phi, *hid, *uv, *vv, *am, *unit, *rbf, *env;
    int *ei, *ej, *deg, *pos, *startp, *sortedp;
    cudaGetSymbolAddress((void**)&s,    g_s);
    cudaGetSymbolAddress((void**)&vA,   g_vA);
    cudaGetSymbolAddress((void**)&vB,   g_vB);
    cudaGetSymbolAddress((void**)&phi,  g_phi);
    cudaGetSymbolAddress((void**)&hid,  g_hid);
    cudaGetSymbolAddress((void**)&uv,   g_uv);
    cudaGetSymbolAddress((void**)&vv,   g_vv);
    cudaGetSymbolAddress((void**)&am,   g_am);
    cudaGetSymbolAddress((void**)&unit, g_unit);
    cudaGetSymbolAddress((void**)&rbf,  g_rbf);
    cudaGetSymbolAddress((void**)&env,  g_env);
    cudaGetSymbolAddress((void**)&ei,   g_ei);
    cudaGetSymbolAddress((void**)&ej,   g_ej);
    cudaGetSymbolAddress((void**)&deg,    g_deg);
    cudaGetSymbolAddress((void**)&pos,    g_pos);
    cudaGetSymbolAddress((void**)&startp, g_start);
    cudaGetSymbolAddress((void**)&sortedp,g_sorted);

    const int TPB = 256;
    // init state
    copy4_kernel<<<(NF/4 + TPB-1)/TPB, TPB>>>((float4*)s, (const float4*)cg_s, NF/4);
    zero4_kernel<<<(3*NF/4 + TPB-1)/TPB, TPB>>>((float4*)vA, 3*NF/4);
    // edge geometry + CSR build
    edge_geom_kernel<<<(EDG + TPB-1)/TPB, TPB>>>(xyz, nbr, unit, rbf, env, ei, ej);
    zeroi_kernel<<<(NN + TPB-1)/TPB, TPB>>>(deg, pos, NN);
    hist_kernel<<<(EDG + TPB-1)/TPB, TPB>>>(ei, deg);
    scan_kernel<<<1, 1024>>>(deg, startp);
    scatter_kernel<<<(EDG + TPB-1)/TPB, TPB>>>(ei, startp, pos, sortedp);

    const int RT = (NN + 127) / 128;   // 157 row tiles
    float* v_cur = vA; float* v_nxt = vB;

    for (int l = 0; l < NCONV; l++) {
        // phi = silu(s @ W1^T + b1) @ W2^T + b2
        mma_gemm_kernel<true , false><<<dim3(1, RT, 1), TPB>>>(
            s, 0, msg_W1 + (size_t)l*FEAT*FEAT, nullptr, msg_b1 + (size_t)l*FEAT,
            hid, nullptr, 0, nullptr, NN, FEAT, FEAT);
        mma_gemm_kernel<false, false><<<dim3(3, RT, 1), TPB>>>(
            hid, 0, msg_W2 + (size_t)l*384*FEAT, nullptr, msg_b2 + (size_t)l*384,
            phi, nullptr, 0, nullptr, NN, 384, FEAT);
        // per-node gather/reduce: updates s in place, writes v_nxt = v_cur + dv
        edge_node_kernel<<<NN, 128>>>(phi, v_cur,
                                      dist_W + (size_t)l*384*NRBF, dist_b + (size_t)l*384,
                                      ej, unit, rbf, env, startp, sortedp,
                                      s, v_nxt);
        // u_v and v_v fused (shared A tile), batched over 3 spatial dims
        mma_gemm_kernel<false, false><<<dim3(2, RT, 3), TPB>>>(
            v_nxt, (size_t)NF, upd_U + (size_t)l*FEAT*FEAT, upd_V + (size_t)l*FEAT*FEAT,
            nullptr, uv, vv, (size_t)NF, nullptr, NN, FEAT, FEAT);
        // a = silu([s|norm(vv)] @ sW1^T + sb1) @ sW2^T + sb2  — xcat inlined into staging
        mma_gemm_kernel<true , true ><<<dim3(1, RT, 1), TPB>>>(
            s, 0, upd_sW1 + (size_t)l*FEAT*256, nullptr, upd_sb1 + (size_t)l*FEAT,
            hid, nullptr, 0, vv, NN, FEAT, 256);
        mma_gemm_kernel<false, false><<<dim3(3, RT, 1), TPB>>>(
            hid, 0, upd_sW2 + (size_t)l*384*FEAT, nullptr, upd_sb2 + (size_t)l*384,
            am, nullptr, 0, nullptr, NN, 384, FEAT);
        // gated update (s and v_nxt in place); last layer also packs output
        update_kernel<<<(NF + TPB-1)/TPB, TPB>>>(uv, vv, am, s, v_nxt,
                                                 (l == NCONV-1) ? out : nullptr);

        float* t = v_cur; v_cur = v_nxt; v_nxt = t;
    }
}

// round 14
// speedup vs baseline: 1.1363x; 1.1363x over previous
#include <cuda_runtime.h>
#include <math.h>
#include <stdint.h>

// ---------------- problem constants ----------------
#define NN      20000      // nodes
#define FEAT    128
#define E0      100000     // undirected edges
#define EDG     200000     // directed (doubled)
#define NRBF    20
#define NCONV   3
#define CUTOFF  20.0f
#define PI_F    3.14159265358979323846f

#define NF      (NN*FEAT)          // 2,560,000
#define N3F     (NN*384)           // 7,680,000

// ---------------- device scratch (no cudaMalloc allowed) ----------------
__device__ float g_s [NF];
__device__ float g_vA[3*NF];
__device__ float g_vB[3*NF];
__device__ float g_phi[N3F];
__device__ float g_hid[NF];
__device__ float g_uv[3*NF];
__device__ float g_vv[3*NF];
__device__ float g_xcat[NN*256];
__device__ float g_am[N3F];
__device__ float g_unit[EDG*3];
__device__ float g_rbf[EDG*NRBF];
__device__ float g_env[EDG];
__device__ int   g_ei[EDG];
__device__ int   g_ej[EDG];
// CSR sort scratch
__device__ int   g_deg[NN];
__device__ int   g_pos[NN];
__device__ int   g_start[NN+1];
__device__ int   g_sorted[EDG];

// ---------------- helpers ----------------
__device__ __forceinline__ float tf32_rna(float x) {
    uint32_t u; asm("cvt.rna.tf32.f32 %0, %1;" : "=r"(u) : "f"(x));
    return __uint_as_float(u);
}
__device__ __forceinline__ void mma_tf32(float* c, const uint32_t* a, uint32_t b0, uint32_t b1) {
    asm volatile(
        "mma.sync.aligned.m16n8k8.row.col.f32.tf32.tf32.f32 "
        "{%0,%1,%2,%3}, {%4,%5,%6,%7}, {%8,%9}, {%0,%1,%2,%3};"
        : "+f"(c[0]), "+f"(c[1]), "+f"(c[2]), "+f"(c[3])
        : "r"(a[0]), "r"(a[1]), "r"(a[2]), "r"(a[3]), "r"(b0), "r"(b1));
}
__device__ __forceinline__ void cp16(uint32_t dst, const void* src, bool pred) {
    int sz = pred ? 16 : 0;
    asm volatile("cp.async.ca.shared.global [%0], [%1], 16, %2;"
                 :: "r"(dst), "l"(src), "r"(sz) : "memory");
}

// ---------------- small utility kernels ----------------
__global__ void copy4_kernel(float4* __restrict__ dst, const float4* __restrict__ src, int n4) {
    int i = blockIdx.x * blockDim.x + threadIdx.x;
    if (i < n4) dst[i] = src[i];
}
__global__ void zero4_kernel(float4* __restrict__ dst, int n4) {
    int i = blockIdx.x * blockDim.x + threadIdx.x;
    if (i < n4) dst[i] = make_float4(0.f,0.f,0.f,0.f);
}
__global__ void zeroi_kernel(int* __restrict__ a, int* __restrict__ b, int n) {
    int i = blockIdx.x * blockDim.x + threadIdx.x;
    if (i < n) { a[i] = 0; b[i] = 0; }
}

// ---------------- edge geometry precompute ----------------
__global__ void edge_geom_kernel(const float* __restrict__ xyz, const int* __restrict__ nbr,
                                 float* __restrict__ unit, float* __restrict__ rbf,
                                 float* __restrict__ env, int* __restrict__ ei, int* __restrict__ ej) {
    int e = blockIdx.x * blockDim.x + threadIdx.x;
    if (e >= EDG) return;
    int p = (e < E0) ? e : (e - E0);
    int a = nbr[p*2], b = nbr[p*2+1];
    int i = (e < E0) ? a : b;
    int j = (e < E0) ? b : a;
    float dx = xyz[j*3+0] - xyz[i*3+0];
    float dy = xyz[j*3+1] - xyz[i*3+1];
    float dz = xyz[j*3+2] - xyz[i*3+2];
    float d  = sqrtf(dx*dx + dy*dy + dz*dz);
    float invd = 1.0f / d;
    unit[e*3+0] = dx*invd; unit[e*3+1] = dy*invd; unit[e*3+2] = dz*invd;
    #pragma unroll
    for (int k = 0; k < NRBF; k++)
        rbf[e*NRBF + k] = sinf((float)(k+1) * PI_F * d / CUTOFF) * invd;
    env[e] = (d < CUTOFF) ? 0.5f * (cosf(PI_F * d / CUTOFF) + 1.0f) : 0.0f;
    ei[e] = i; ej[e] = j;
}

// ---------------- CSR build: histogram, scan, scatter ----------------
__global__ void hist_kernel(const int* __restrict__ ei, int* __restrict__ deg) {
    int e = blockIdx.x * blockDim.x + threadIdx.x;
    if (e < EDG) atomicAdd(&deg[ei[e]], 1);
}
__global__ void scan_kernel(const int* __restrict__ deg, int* __restrict__ start) {
    __shared__ int ssum[1024];
    const int tid = threadIdx.x;
    const int CH = (NN + 1023) / 1024;   // 20
    int base = tid * CH;
    int local = 0;
    for (int k = 0; k < CH; k++) {
        int idx = base + k;
        if (idx < NN) local += deg[idx];
    }
    ssum[tid] = local;
    __syncthreads();
    for (int off = 1; off < 1024; off <<= 1) {
        int t = (tid >= off) ? ssum[tid - off] : 0;
        __syncthreads();
        ssum[tid] += t;
        __syncthreads();
    }
    int run = ssum[tid] - local;
    for (int k = 0; k < CH; k++) {
        int idx = base + k;
        if (idx < NN) { start[idx] = run; run += deg[idx]; }
    }
    if (tid == 1023) start[NN] = ssum[1023];
}
__global__ void scatter_kernel(const int* __restrict__ ei, const int* __restrict__ start,
                               int* __restrict__ pos, int* __restrict__ sorted) {
    int e = blockIdx.x * blockDim.x + threadIdx.x;
    if (e >= EDG) return;
    int i = ei[e];
    int p = start[i] + atomicAdd(&pos[i], 1);
    sorted[p] = e;
}

// =====================================================================
// mma.sync TF32x3 GEMM, cp.async 2-stage pipeline, reg-side hi/lo split.
// (R6/R10 winner — unchanged.)
// =====================================================================
#define PITCH 20
template<bool SILU>
__global__ void __launch_bounds__(256)
mma_gemm_kernel(const float* __restrict__ A, size_t aStride,
                const float* __restrict__ W, const float* __restrict__ W2,
                const float* __restrict__ bias,
                float* __restrict__ C, float* __restrict__ C2, size_t cStride,
                int Nrows, int Mcols, int K) {
    __shared__ float As[2][128 * PITCH];
    __shared__ float Bs[2][128 * PITCH];

    const int tid = threadIdx.x;
    const int wid = tid >> 5;
    const int lid = tid & 31;
    const int tq  = lid >> 2;
    const int tr  = lid & 3;
    const int warpRow = (wid & 3) * 32;
    const int warpCol = (wid >> 2) * 64;
    const int rowBase = blockIdx.y * 128;

    const int colTiles = (Mcols + 127) >> 7;
    int bx = blockIdx.x;
    const float* Wsel = W;
    float* Csel = C;
    if (W2 != nullptr && bx >= colTiles) { Wsel = W2; Csel = C2; bx -= colTiles; }
    const int colBase = bx * 128;

    A    += (size_t)blockIdx.z * aStride;
    Csel += (size_t)blockIdx.z * cStride;
    const float* Wt = Wsel + (size_t)colBase * K;

    const uint32_t aSm0 = (uint32_t)__cvta_generic_to_shared(&As[0][0]);
    const uint32_t aSm1 = (uint32_t)__cvta_generic_to_shared(&As[1][0]);
    const uint32_t bSm0 = (uint32_t)__cvta_generic_to_shared(&Bs[0][0]);
    const uint32_t bSm1 = (uint32_t)__cvta_generic_to_shared(&Bs[1][0]);

    const int ldRow0 = tid >> 2;
    const int ldQ    = (tid & 3) * 4;

    float acc[2][8][4];
    #pragma unroll
    for (int mf = 0; mf < 2; mf++)
        #pragma unroll
        for (int nf = 0; nf < 8; nf++)
            #pragma unroll
            for (int u = 0; u < 4; u++) acc[mf][nf][u] = 0.f;

    const int nch = K >> 4;

    auto issue_stage = [&](int c, int buf) {
        const int k0 = c * 16;
        uint32_t aSm = buf ? aSm1 : aSm0;
        uint32_t bSm = buf ? bSm1 : bSm0;
        #pragma unroll
        for (int half = 0; half < 2; half++) {
            int row = half * 64 + ldRow0;
            int r = rowBase + row;
            uint32_t soff = (uint32_t)(row * PITCH + ldQ) * 4u;
            cp16(aSm + soff, &A[(size_t)r * K + k0 + ldQ], r < Nrows);
            cp16(bSm + soff, &Wt[(size_t)row * K + k0 + ldQ], true);
        }
        asm volatile("cp.async.commit_group;" ::: "memory");
    };

    issue_stage(0, 0);

    for (int c = 0; c < nch; c++) {
        if (c + 1 < nch) {
            issue_stage(c + 1, (c + 1) & 1);
            asm volatile("cp.async.wait_group 1;" ::: "memory");
        } else {
            asm volatile("cp.async.wait_group 0;" ::: "memory");
        }
        __syncthreads();

        const float* Ab = As[c & 1];
        const float* Bb = Bs[c & 1];

        #pragma unroll
        for (int ks = 0; ks < 2; ks++) {
            const int kc = ks * 8;
            uint32_t ah[2][4], al[2][4];
            #pragma unroll
            for (int mf = 0; mf < 2; mf++) {
                int r0 = warpRow + mf * 16 + tq;
                float a0 = Ab[(r0    ) * PITCH + kc + tr    ];
                float a1 = Ab[(r0 + 8) * PITCH + kc + tr    ];
                float a2 = Ab[(r0    ) * PITCH + kc + tr + 4];
                float a3 = Ab[(r0 + 8) * PITCH + kc + tr + 4];
                float h0 = tf32_rna(a0), h1 = tf32_rna(a1), h2 = tf32_rna(a2), h3 = tf32_rna(a3);
                ah[mf][0] = __float_as_uint(h0); al[mf][0] = __float_as_uint(a0 - h0);
                ah[mf][1] = __float_as_uint(h1); al[mf][1] = __float_as_uint(a1 - h1);
                ah[mf][2] = __float_as_uint(h2); al[mf][2] = __float_as_uint(a2 - h2);
                ah[mf][3] = __float_as_uint(h3); al[mf][3] = __float_as_uint(a3 - h3);
            }
            #pragma unroll
            for (int nf = 0; nf < 8; nf++) {
                int c0 = warpCol + nf * 8 + tq;
                float b0 = Bb[c0 * PITCH + kc + tr    ];
                float b1 = Bb[c0 * PITCH + kc + tr + 4];
                float bh0f = tf32_rna(b0), bh1f = tf32_rna(b1);
                uint32_t bh0 = __float_as_uint(bh0f);
                uint32_t bh1 = __float_as_uint(bh1f);
                uint32_t bl0 = __float_as_uint(b0 - bh0f);
                uint32_t bl1 = __float_as_uint(b1 - bh1f);
                #pragma unroll
                for (int mf = 0; mf < 2; mf++) {
                    mma_tf32(acc[mf][nf], ah[mf], bh0, bh1);
                    mma_tf32(acc[mf][nf], al[mf], bh0, bh1);
                    mma_tf32(acc[mf][nf], ah[mf], bl0, bl1);
                }
            }
        }
        __syncthreads();
    }

    #pragma unroll
    for (int mf = 0; mf < 2; mf++) {
        int r0 = rowBase + warpRow + mf * 16 + tq;
        #pragma unroll
        for (int nf = 0; nf < 8; nf++) {
            int cb = colBase + warpCol + nf * 8 + tr * 2;
            float b0 = bias ? bias[cb] : 0.f;
            float b1 = bias ? bias[cb + 1] : 0.f;
            float v0 = acc[mf][nf][0] + b0;
            float v1 = acc[mf][nf][1] + b1;
            float v2 = acc[mf][nf][2] + b0;
            float v3 = acc[mf][nf][3] + b1;
            if (SILU) {
                v0 = v0 / (1.f + expf(-v0));
                v1 = v1 / (1.f + expf(-v1));
                v2 = v2 / (1.f + expf(-v2));
                v3 = v3 / (1.f + expf(-v3));
            }
            if (r0 < Nrows)      *(float2*)&Csel[(size_t)r0      * Mcols + cb] = make_float2(v0, v1);
            if (r0 + 8 < Nrows)  *(float2*)&Csel[(size_t)(r0 + 8) * Mcols + cb] = make_float2(v2, v3);
        }
    }
}

// ---------------- per-node edge gather, PERSISTENT-STRIDED ----------------
// Each CTA loads the 60 dist_W weights into registers ONCE, then loops over
// nodes n = blockIdx.x, += gridDim.x — amortizing the prologue ~8.5x vs the
// one-CTA-per-node version. Per-node math identical (bit-exact to R10).
#define EDGE_GRID 2368
__global__ void __launch_bounds__(128)
edge_node_kernel(const float* __restrict__ phi,
                 const float* __restrict__ v_old,
                 const float* __restrict__ distW,
                 const float* __restrict__ distb,
                 const int* __restrict__ ej,
                 const float* __restrict__ unit, const float* __restrict__ rbf,
                 const float* __restrict__ env,
                 const int* __restrict__ start, const int* __restrict__ sorted,
                 float* __restrict__ s, float* __restrict__ v_new) {
    const int f = threadIdx.x;

    float w[3][NRBF];
    float bch[3];
    #pragma unroll
    for (int c = 0; c < 3; c++) {
        const float4* src = (const float4*)&distW[(c * 128 + f) * NRBF];
        #pragma unroll
        for (int q = 0; q < 5; q++) {
            float4 v4 = src[q];
            w[c][q*4+0] = v4.x; w[c][q*4+1] = v4.y; w[c][q*4+2] = v4.z; w[c][q*4+3] = v4.w;
        }
        bch[c] = distb[c * 128 + f];
    }

    for (int n = blockIdx.x; n < NN; n += gridDim.x) {
        const size_t nb = (size_t)n * 128 + f;
        float sAcc = s[nb];
        float a0 = v_old[nb];
        float a1 = v_old[NF + nb];
        float a2 = v_old[2*NF + nb];

        const int e0 = start[n], e1 = start[n + 1];
        for (int k = e0; k < e1; k++) {
            int e = sorted[k];
            int j = ej[e];
            float rb[NRBF];
            {
                const float4* src = (const float4*)&rbf[e * NRBF];
                #pragma unroll
                for (int q = 0; q < 5; q++) {
                    float4 v4 = src[q];
                    rb[q*4+0] = v4.x; rb[q*4+1] = v4.y; rb[q*4+2] = v4.z; rb[q*4+3] = v4.w;
                }
            }
            float ev = env[e];
            float u0 = unit[e*3+0], u1 = unit[e*3+1], u2 = unit[e*3+2];

            const float* phij = phi + (size_t)j * 384 + f;
            float inv[3];
            #pragma unroll
            for (int c = 0; c < 3; c++) {
                float acc = bch[c];
                #pragma unroll
                for (int kk = 0; kk < NRBF; kk++) acc += rb[kk] * w[c][kk];
                inv[c] = phij[c * 128] * (acc * ev);
            }

            const size_t jb = (size_t)j * 128 + f;
            sAcc += inv[1];
            a0 += inv[2]*u0 + inv[0]*v_old[jb];
            a1 += inv[2]*u1 + inv[0]*v_old[NF + jb];
            a2 += inv[2]*u2 + inv[0]*v_old[2*NF + jb];
        }

        s[nb] = sAcc;
        v_new[nb]        = a0;
        v_new[NF + nb]   = a1;
        v_new[2*NF + nb] = a2;
    }
}

// ---------------- xcat = [s, ||v_v||] ----------------
__global__ void xcat_kernel(const float* __restrict__ s, const float* __restrict__ vv,
                            float* __restrict__ xcat) {
    int idx = blockIdx.x * blockDim.x + threadIdx.x;
    if (idx >= NF) return;
    int n = idx >> 7, f = idx & 127;
    float a = vv[idx], b = vv[NF + idx], c = vv[2*NF + idx];
    xcat[(size_t)n*256 + f]       = s[idx];
    xcat[(size_t)n*256 + 128 + f] = sqrtf(a*a + b*b + c*c);
}

// ---------------- final gated update (in place) ----------------
__global__ void update_kernel(const float* __restrict__ uv, const float* __restrict__ vv,
                              const float* __restrict__ am,
                              float* __restrict__ s, float* __restrict__ v) {
    int idx = blockIdx.x * blockDim.x + threadIdx.x;
    if (idx >= NF) return;
    int n = idx >> 7, f = idx & 127;
    float dot = uv[idx]*vv[idx] + uv[NF+idx]*vv[NF+idx] + uv[2*NF+idx]*vv[2*NF+idx];
    float a0 = am[(size_t)n*384 + f];
    float a1 = am[(size_t)n*384 + 128 + f];
    float a2 = am[(size_t)n*384 + 256 + f];
    s[idx] += dot * a1 + a2;
    #pragma unroll
    for (int d = 0; d < 3; d++)
        v[(size_t)d*NF + idx] += uv[(size_t)d*NF + idx] * a0;
}

// ---------------- pack output: s flat, then v as (N,128,3) ----------------
__global__ void output_kernel(const float* __restrict__ s, const float* __restrict__ v,
                              float* __restrict__ out) {
    int idx = blockIdx.x * blockDim.x + threadIdx.x;
    if (idx >= NF) return;
    int n = idx >> 7, f = idx & 127;
    out[idx] = s[idx];
    #pragma unroll
    for (int d = 0; d < 3; d++)
        out[(size_t)NF + (size_t)n*384 + f*3 + d] = v[(size_t)d*NF + idx];
}

// ---------------- host orchestration ----------------
extern "C" void kernel_launch(void* const* d_in, const int* in_sizes, int n_in,
                              void* d_out, int out_size) {
    const float* xyz    = (const float*)d_in[0];
    const int*   nbr    = (const int*)  d_in[1];
    const float* cg_s   = (const float*)d_in[2];
    const float* msg_W1 = (const float*)d_in[3];
    const float* msg_b1 = (const float*)d_in[4];
    const float* msg_W2 = (const float*)d_in[5];
    const float* msg_b2 = (const float*)d_in[6];
    const float* dist_W = (const float*)d_in[7];
    const float* dist_b = (const float*)d_in[8];
    const float* upd_U  = (const float*)d_in[9];
    const float* upd_V  = (const float*)d_in[10];
    const float* upd_sW1= (const float*)d_in[11];
    const float* upd_sb1= (const float*)d_in[12];
    const float* upd_sW2= (const float*)d_in[13];
    const float* upd_sb2= (const float*)d_in[14];
    float* out = (float*)d_out;

    float *s, *vA, *vB, *phi, *hid, *uv, *vv, *xcat, *am, *unit, *rbf, *env;
    int *ei, *ej, *deg, *pos, *startp, *sortedp;
    cudaGetSymbolAddress((void**)&s,    g_s);
    cudaGetSymbolAddress((void**)&vA,   g_vA);
    cudaGetSymbolAddress((void**)&vB,   g_vB);
    cudaGetSymbolAddress((void**)&phi,  g_phi);
    cudaGetSymbolAddress((void**)&hid,  g_hid);
    cudaGetSymbolAddress((void**)&uv,   g_uv);
    cudaGetSymbolAddress((void**)&vv,   g_vv);
    cudaGetSymbolAddress((void**)&xcat, g_xcat);
    cudaGetSymbolAddress((void**)&am,   g_am);
    cudaGetSymbolAddress((void**)&unit, g_unit);
    cudaGetSymbolAddress((void**)&rbf,  g_rbf);
    cudaGetSymbolAddress((void**)&env,  g_env);
    cudaGetSymbolAddress((void**)&ei,   g_ei);
    cudaGetSymbolAddress((void**)&ej,   g_ej);
    cudaGetSymbolAddress((void**)&deg,    g_deg);
    cudaGetSymbolAddress((void**)&pos,    g_pos);
    cudaGetSymbolAddress((void**)&startp, g_start);
    cudaGetSymbolAddress((void**)&sortedp,g_sorted);

    const int TPB = 256;
    // init state
    copy4_kernel<<<(NF/4 + TPB-1)/TPB, TPB>>>((float4*)s, (const float4*)cg_s, NF/4);
    zero4_kernel<<<(3*NF/4 + TPB-1)/TPB, TPB>>>((float4*)vA, 3*NF/4);
    // edge geometry + CSR build
    edge_geom_kernel<<<(EDG + TPB-1)/TPB, TPB>>>(xyz, nbr, unit, rbf, env, ei, ej);
    zeroi_kernel<<<(NN + TPB-1)/TPB, TPB>>>(deg, pos, NN);
    hist_kernel<<<(EDG + TPB-1)/TPB, TPB>>>(ei, deg);
    scan_kernel<<<1, 1024>>>(deg, startp);
    scatter_kernel<<<(EDG + TPB-1)/TPB, TPB>>>(ei, startp, pos, sortedp);

    const int RT = (NN + 127) / 128;   // 157 row tiles
    float* v_cur = vA; float* v_nxt = vB;

    for (int l = 0; l < NCONV; l++) {
        // phi = silu(s @ W1^T + b1) @ W2^T + b2
        mma_gemm_kernel<true ><<<dim3(1, RT, 1), TPB>>>(
            s, 0, msg_W1 + (size_t)l*FEAT*FEAT, nullptr, msg_b1 + (size_t)l*FEAT,
            hid, nullptr, 0, NN, FEAT, FEAT);
        mma_gemm_kernel<false><<<dim3(3, RT, 1), TPB>>>(
            hid, 0, msg_W2 + (size_t)l*384*FEAT, nullptr, msg_b2 + (size_t)l*384,
            phi, nullptr, 0, NN, 384, FEAT);
        // per-node gather/reduce (persistent CTAs): s in place, v_nxt = v_cur + dv
        edge_node_kernel<<<EDGE_GRID, 128>>>(phi, v_cur,
                                             dist_W + (size_t)l*384*NRBF, dist_b + (size_t)l*384,
                                             ej, unit, rbf, env, startp, sortedp,
                                             s, v_nxt);
        // u_v and v_v fused (shared A tile), batched over 3 spatial dims
        mma_gemm_kernel<false><<<dim3(2, RT, 3), TPB>>>(
            v_nxt, (size_t)NF, upd_U + (size_t)l*FEAT*FEAT, upd_V + (size_t)l*FEAT*FEAT,
            nullptr, uv, vv, (size_t)NF, NN, FEAT, FEAT);
        // xcat = [s, ||v_v||]
        xcat_kernel<<<(NF + TPB-1)/TPB, TPB>>>(s, vv, xcat);
        // a = silu(xcat @ sW1^T + sb1) @ sW2^T + sb2
        mma_gemm_kernel<true ><<<dim3(1, RT, 1), TPB>>>(
            xcat, 0, upd_sW1 + (size_t)l*FEAT*256, nullptr, upd_sb1 + (size_t)l*FEAT,
            hid, nullptr, 0, NN, FEAT, 256);
        mma_gemm_kernel<false><<<dim3(3, RT, 1), TPB>>>(
            hid, 0, upd_sW2 + (size_t)l*384*FEAT, nullptr, upd_sb2 + (size_t)l*384,
            am, nullptr, 0, NN, 384, FEAT);
        // gated update (s and v_nxt in place)
        update_kernel<<<(NF + TPB-1)/TPB, TPB>>>(uv, vv, am, s, v_nxt);

        float* t = v_cur; v_cur = v_nxt; v_nxt = t;
    }

    output_kernel<<<(NF + TPB-1)/TPB, TPB>>>(s, v_cur, out);
}

// round 15
// speedup vs baseline: 1.2149x; 1.0691x over previous
#include <cuda_runtime.h>
#include <math.h>
#include <stdint.h>

// ---------------- problem constants ----------------
#define NN      20000      // nodes
#define FEAT    128
#define E0      100000     // undirected edges
#define EDG     200000     // directed (doubled)
#define NRBF    20
#define NCONV   3
#define CUTOFF  20.0f
#define PI_F    3.14159265358979323846f

#define NF      (NN*FEAT)          // 2,560,000
#define N3F     (NN*384)           // 7,680,000

// ---------------- device scratch (no cudaMalloc allowed) ----------------
__device__ float g_s [NF];
__device__ float g_vA[3*NF];
__device__ float g_vB[3*NF];
__device__ float g_phi[N3F];
__device__ float g_hid[NF];
__device__ float g_uv[3*NF];
__device__ float g_vv[3*NF];
__device__ float g_xcat[NN*256];
__device__ float g_am[N3F];
__device__ float g_unit[EDG*3];
__device__ float g_rbf[EDG*NRBF];
__device__ float g_env[EDG];
__device__ int   g_ei[EDG];
__device__ int   g_ej[EDG];
// CSR sort scratch
__device__ int   g_deg[NN];
__device__ int   g_pos[NN];
__device__ int   g_start[NN+1];
__device__ int   g_sorted[EDG];

// ---------------- helpers ----------------
__device__ __forceinline__ float tf32_rna(float x) {
    uint32_t u; asm("cvt.rna.tf32.f32 %0, %1;" : "=r"(u) : "f"(x));
    return __uint_as_float(u);
}
__device__ __forceinline__ void mma_tf32(float* c, const uint32_t* a, uint32_t b0, uint32_t b1) {
    asm volatile(
        "mma.sync.aligned.m16n8k8.row.col.f32.tf32.tf32.f32 "
        "{%0,%1,%2,%3}, {%4,%5,%6,%7}, {%8,%9}, {%0,%1,%2,%3};"
        : "+f"(c[0]), "+f"(c[1]), "+f"(c[2]), "+f"(c[3])
        : "r"(a[0]), "r"(a[1]), "r"(a[2]), "r"(a[3]), "r"(b0), "r"(b1));
}
__device__ __forceinline__ void cp16(uint32_t dst, const void* src, bool pred) {
    int sz = pred ? 16 : 0;
    asm volatile("cp.async.ca.shared.global [%0], [%1], 16, %2;"
                 :: "r"(dst), "l"(src), "r"(sz) : "memory");
}

// ---------------- small utility kernels ----------------
__global__ void copy4_kernel(float4* __restrict__ dst, const float4* __restrict__ src, int n4) {
    int i = blockIdx.x * blockDim.x + threadIdx.x;
    if (i < n4) dst[i] = src[i];
}
__global__ void zero4_kernel(float4* __restrict__ dst, int n4) {
    int i = blockIdx.x * blockDim.x + threadIdx.x;
    if (i < n4) dst[i] = make_float4(0.f,0.f,0.f,0.f);
}
__global__ void zeroi_kernel(int* __restrict__ a, int* __restrict__ b, int n) {
    int i = blockIdx.x * blockDim.x + threadIdx.x;
    if (i < n) { a[i] = 0; b[i] = 0; }
}

// ---------------- edge geometry precompute ----------------
__global__ void edge_geom_kernel(const float* __restrict__ xyz, const int* __restrict__ nbr,
                                 float* __restrict__ unit, float* __restrict__ rbf,
                                 float* __restrict__ env, int* __restrict__ ei, int* __restrict__ ej) {
    int e = blockIdx.x * blockDim.x + threadIdx.x;
    if (e >= EDG) return;
    int p = (e < E0) ? e : (e - E0);
    int a = nbr[p*2], b = nbr[p*2+1];
    int i = (e < E0) ? a : b;
    int j = (e < E0) ? b : a;
    float dx = xyz[j*3+0] - xyz[i*3+0];
    float dy = xyz[j*3+1] - xyz[i*3+1];
    float dz = xyz[j*3+2] - xyz[i*3+2];
    float d  = sqrtf(dx*dx + dy*dy + dz*dz);
    float invd = 1.0f / d;
    unit[e*3+0] = dx*invd; unit[e*3+1] = dy*invd; unit[e*3+2] = dz*invd;
    #pragma unroll
    for (int k = 0; k < NRBF; k++)
        rbf[e*NRBF + k] = sinf((float)(k+1) * PI_F * d / CUTOFF) * invd;
    env[e] = (d < CUTOFF) ? 0.5f * (cosf(PI_F * d / CUTOFF) + 1.0f) : 0.0f;
    ei[e] = i; ej[e] = j;
}

// ---------------- CSR build: histogram, scan, scatter ----------------
__global__ void hist_kernel(const int* __restrict__ ei, int* __restrict__ deg) {
    int e = blockIdx.x * blockDim.x + threadIdx.x;
    if (e < EDG) atomicAdd(&deg[ei[e]], 1);
}
__global__ void scan_kernel(const int* __restrict__ deg, int* __restrict__ start) {
    __shared__ int ssum[1024];
    const int tid = threadIdx.x;
    const int CH = (NN + 1023) / 1024;   // 20
    int base = tid * CH;
    int local = 0;
    for (int k = 0; k < CH; k++) {
        int idx = base + k;
        if (idx < NN) local += deg[idx];
    }
    ssum[tid] = local;
    __syncthreads();
    for (int off = 1; off < 1024; off <<= 1) {
        int t = (tid >= off) ? ssum[tid - off] : 0;
        __syncthreads();
        ssum[tid] += t;
        __syncthreads();
    }
    int run = ssum[tid] - local;
    for (int k = 0; k < CH; k++) {
        int idx = base + k;
        if (idx < NN) { start[idx] = run; run += deg[idx]; }
    }
    if (tid == 1023) start[NN] = ssum[1023];
}
__global__ void scatter_kernel(const int* __restrict__ ei, const int* __restrict__ start,
                               int* __restrict__ pos, int* __restrict__ sorted) {
    int e = blockIdx.x * blockDim.x + threadIdx.x;
    if (e >= EDG) return;
    int i = ei[e];
    int p = start[i] + atomicAdd(&pos[i], 1);
    sorted[p] = e;
}

// =====================================================================
// mma.sync TF32x3 GEMM, cp.async 3-STAGE pipeline, reg-side hi/lo split.
// Identical to R10 winner except pipeline depth 2 -> 3 (dynamic smem).
// =====================================================================
#define PITCH 20
#define NSTAGE 3
#define STAGE_F (2 * 128 * PITCH)                  // A + B planes per stage
#define GEMM_SMEM_BYTES (NSTAGE * STAGE_F * 4)     // 61,440 bytes

template<bool SILU>
__global__ void __launch_bounds__(256)
mma_gemm_kernel(const float* __restrict__ A, size_t aStride,
                const float* __restrict__ W, const float* __restrict__ W2,
                const float* __restrict__ bias,
                float* __restrict__ C, float* __restrict__ C2, size_t cStride,
                int Nrows, int Mcols, int K) {
    extern __shared__ float sm[];

    const int tid = threadIdx.x;
    const int wid = tid >> 5;
    const int lid = tid & 31;
    const int tq  = lid >> 2;
    const int tr  = lid & 3;
    const int warpRow = (wid & 3) * 32;
    const int warpCol = (wid >> 2) * 64;
    const int rowBase = blockIdx.y * 128;

    const int colTiles = (Mcols + 127) >> 7;
    int bx = blockIdx.x;
    const float* Wsel = W;
    float* Csel = C;
    if (W2 != nullptr && bx >= colTiles) { Wsel = W2; Csel = C2; bx -= colTiles; }
    const int colBase = bx * 128;

    A    += (size_t)blockIdx.z * aStride;
    Csel += (size_t)blockIdx.z * cStride;
    const float* Wt = Wsel + (size_t)colBase * K;

    const uint32_t smBase = (uint32_t)__cvta_generic_to_shared(sm);

    const int ldRow0 = tid >> 2;
    const int ldQ    = (tid & 3) * 4;

    float acc[2][8][4];
    #pragma unroll
    for (int mf = 0; mf < 2; mf++)
        #pragma unroll
        for (int nf = 0; nf < 8; nf++)
            #pragma unroll
            for (int u = 0; u < 4; u++) acc[mf][nf][u] = 0.f;

    const int nch = K >> 4;

    auto issue_stage = [&](int c) {
        const int k0 = c * 16;
        const int st = c % NSTAGE;
        uint32_t aSm = smBase + (uint32_t)(st * STAGE_F) * 4u;
        uint32_t bSm = aSm + (uint32_t)(128 * PITCH) * 4u;
        #pragma unroll
        for (int half = 0; half < 2; half++) {
            int row = half * 64 + ldRow0;
            int r = rowBase + row;
            uint32_t soff = (uint32_t)(row * PITCH + ldQ) * 4u;
            cp16(aSm + soff, &A[(size_t)r * K + k0 + ldQ], r < Nrows);
            cp16(bSm + soff, &Wt[(size_t)row * K + k0 + ldQ], true);
        }
        asm volatile("cp.async.commit_group;" ::: "memory");
    };

    // prologue: fill 2 stages
    issue_stage(0);
    if (nch > 1) issue_stage(1);

    for (int c = 0; c < nch; c++) {
        if (c + 2 < nch) {
            issue_stage(c + 2);
            asm volatile("cp.async.wait_group 2;" ::: "memory");
        } else if (c + 1 < nch) {
            asm volatile("cp.async.wait_group 1;" ::: "memory");
        } else {
            asm volatile("cp.async.wait_group 0;" ::: "memory");
        }
        __syncthreads();

        const float* Ab = sm + (c % NSTAGE) * STAGE_F;
        const float* Bb = Ab + 128 * PITCH;

        #pragma unroll
        for (int ks = 0; ks < 2; ks++) {
            const int kc = ks * 8;
            uint32_t ah[2][4], al[2][4];
            #pragma unroll
            for (int mf = 0; mf < 2; mf++) {
                int r0 = warpRow + mf * 16 + tq;
                float a0 = Ab[(r0    ) * PITCH + kc + tr    ];
                float a1 = Ab[(r0 + 8) * PITCH + kc + tr    ];
                float a2 = Ab[(r0    ) * PITCH + kc + tr + 4];
                float a3 = Ab[(r0 + 8) * PITCH + kc + tr + 4];
                float h0 = tf32_rna(a0), h1 = tf32_rna(a1), h2 = tf32_rna(a2), h3 = tf32_rna(a3);
                ah[mf][0] = __float_as_uint(h0); al[mf][0] = __float_as_uint(a0 - h0);
                ah[mf][1] = __float_as_uint(h1); al[mf][1] = __float_as_uint(a1 - h1);
                ah[mf][2] = __float_as_uint(h2); al[mf][2] = __float_as_uint(a2 - h2);
                ah[mf][3] = __float_as_uint(h3); al[mf][3] = __float_as_uint(a3 - h3);
            }
            #pragma unroll
            for (int nf = 0; nf < 8; nf++) {
                int c0 = warpCol + nf * 8 + tq;
                float b0 = Bb[c0 * PITCH + kc + tr    ];
                float b1 = Bb[c0 * PITCH + kc + tr + 4];
                float bh0f = tf32_rna(b0), bh1f = tf32_rna(b1);
                uint32_t bh0 = __float_as_uint(bh0f);
                uint32_t bh1 = __float_as_uint(bh1f);
                uint32_t bl0 = __float_as_uint(b0 - bh0f);
                uint32_t bl1 = __float_as_uint(b1 - bh1f);
                #pragma unroll
                for (int mf = 0; mf < 2; mf++) {
                    mma_tf32(acc[mf][nf], ah[mf], bh0, bh1);
                    mma_tf32(acc[mf][nf], al[mf], bh0, bh1);
                    mma_tf32(acc[mf][nf], ah[mf], bl0, bl1);
                }
            }
        }
        __syncthreads();
    }

    #pragma unroll
    for (int mf = 0; mf < 2; mf++) {
        int r0 = rowBase + warpRow + mf * 16 + tq;
        #pragma unroll
        for (int nf = 0; nf < 8; nf++) {
            int cb = colBase + warpCol + nf * 8 + tr * 2;
            float b0 = bias ? bias[cb] : 0.f;
            float b1 = bias ? bias[cb + 1] : 0.f;
            float v0 = acc[mf][nf][0] + b0;
            float v1 = acc[mf][nf][1] + b1;
            float v2 = acc[mf][nf][2] + b0;
            float v3 = acc[mf][nf][3] + b1;
            if (SILU) {
                v0 = v0 / (1.f + expf(-v0));
                v1 = v1 / (1.f + expf(-v1));
                v2 = v2 / (1.f + expf(-v2));
                v3 = v3 / (1.f + expf(-v3));
            }
            if (r0 < Nrows)      *(float2*)&Csel[(size_t)r0      * Mcols + cb] = make_float2(v0, v1);
            if (r0 + 8 < Nrows)  *(float2*)&Csel[(size_t)(r0 + 8) * Mcols + cb] = make_float2(v2, v3);
        }
    }
}

// ---------------- per-node edge gather (R10 winner — one CTA per node) ----------------
__global__ void __launch_bounds__(128)
edge_node_kernel(const float* __restrict__ phi,
                 const float* __restrict__ v_old,
                 const float* __restrict__ distW,
                 const float* __restrict__ distb,
                 const int* __restrict__ ej,
                 const float* __restrict__ unit, const float* __restrict__ rbf,
                 const float* __restrict__ env,
                 const int* __restrict__ start, const int* __restrict__ sorted,
                 float* __restrict__ s, float* __restrict__ v_new) {
    const int n = blockIdx.x;
    const int f = threadIdx.x;

    float w[3][NRBF];
    float bch[3];
    #pragma unroll
    for (int c = 0; c < 3; c++) {
        const float4* src = (const float4*)&distW[(c * 128 + f) * NRBF];
        #pragma unroll
        for (int q = 0; q < 5; q++) {
            float4 v4 = src[q];
            w[c][q*4+0] = v4.x; w[c][q*4+1] = v4.y; w[c][q*4+2] = v4.z; w[c][q*4+3] = v4.w;
        }
        bch[c] = distb[c * 128 + f];
    }

    const size_t nb = (size_t)n * 128 + f;
    float sAcc = s[nb];
    float a0 = v_old[nb];
    float a1 = v_old[NF + nb];
    float a2 = v_old[2*NF + nb];

    const int e0 = start[n], e1 = start[n + 1];
    for (int k = e0; k < e1; k++) {
        int e = sorted[k];
        int j = ej[e];
        float rb[NRBF];
        {
            const float4* src = (const float4*)&rbf[e * NRBF];
            #pragma unroll
            for (int q = 0; q < 5; q++) {
                float4 v4 = src[q];
                rb[q*4+0] = v4.x; rb[q*4+1] = v4.y; rb[q*4+2] = v4.z; rb[q*4+3] = v4.w;
            }
        }
        float ev = env[e];
        float u0 = unit[e*3+0], u1 = unit[e*3+1], u2 = unit[e*3+2];

        const float* phij = phi + (size_t)j * 384 + f;
        float inv[3];
        #pragma unroll
        for (int c = 0; c < 3; c++) {
            float acc = bch[c];
            #pragma unroll
            for (int kk = 0; kk < NRBF; kk++) acc += rb[kk] * w[c][kk];
            inv[c] = phij[c * 128] * (acc * ev);
        }

        const size_t jb = (size_t)j * 128 + f;
        sAcc += inv[1];
        a0 += inv[2]*u0 + inv[0]*v_old[jb];
        a1 += inv[2]*u1 + inv[0]*v_old[NF + jb];
        a2 += inv[2]*u2 + inv[0]*v_old[2*NF + jb];
    }

    s[nb] = sAcc;
    v_new[nb]        = a0;
    v_new[NF + nb]   = a1;
    v_new[2*NF + nb] = a2;
}

// ---------------- xcat = [s, ||v_v||] ----------------
__global__ void xcat_kernel(const float* __restrict__ s, const float* __restrict__ vv,
                            float* __restrict__ xcat) {
    int idx = blockIdx.x * blockDim.x + threadIdx.x;
    if (idx >= NF) return;
    int n = idx >> 7, f = idx & 127;
    float a = vv[idx], b = vv[NF + idx], c = vv[2*NF + idx];
    xcat[(size_t)n*256 + f]       = s[idx];
    xcat[(size_t)n*256 + 128 + f] = sqrtf(a*a + b*b + c*c);
}

// ---------------- final gated update (in place) ----------------
__global__ void update_kernel(const float* __restrict__ uv, const float* __restrict__ vv,
                              const float* __restrict__ am,
                              float* __restrict__ s, float* __restrict__ v) {
    int idx = blockIdx.x * blockDim.x + threadIdx.x;
    if (idx >= NF) return;
    int n = idx >> 7, f = idx & 127;
    float dot = uv[idx]*vv[idx] + uv[NF+idx]*vv[NF+idx] + uv[2*NF+idx]*vv[2*NF+idx];
    float a0 = am[(size_t)n*384 + f];
    float a1 = am[(size_t)n*384 + 128 + f];
    float a2 = am[(size_t)n*384 + 256 + f];
    s[idx] += dot * a1 + a2;
    #pragma unroll
    for (int d = 0; d < 3; d++)
        v[(size_t)d*NF + idx] += uv[(size_t)d*NF + idx] * a0;
}

// ---------------- pack output: s flat, then v as (N,128,3) ----------------
__global__ void output_kernel(const float* __restrict__ s, const float* __restrict__ v,
                              float* __restrict__ out) {
    int idx = blockIdx.x * blockDim.x + threadIdx.x;
    if (idx >= NF) return;
    int n = idx >> 7, f = idx & 127;
    out[idx] = s[idx];
    #pragma unroll
    for (int d = 0; d < 3; d++)
        out[(size_t)NF + (size_t)n*384 + f*3 + d] = v[(size_t)d*NF + idx];
}

// ---------------- host orchestration ----------------
extern "C" void kernel_launch(void* const* d_in, const int* in_sizes, int n_in,
                              void* d_out, int out_size) {
    const float* xyz    = (const float*)d_in[0];
    const int*   nbr    = (const int*)  d_in[1];
    const float* cg_s   = (const float*)d_in[2];
    const float* msg_W1 = (const float*)d_in[3];
    const float* msg_b1 = (const float*)d_in[4];
    const float* msg_W2 = (const float*)d_in[5];
    const float* msg_b2 = (const float*)d_in[6];
    const float* dist_W = (const float*)d_in[7];
    const float* dist_b = (const float*)d_in[8];
    const float* upd_U  = (const float*)d_in[9];
    const float* upd_V  = (const float*)d_in[10];
    const float* upd_sW1= (const float*)d_in[11];
    const float* upd_sb1= (const float*)d_in[12];
    const float* upd_sW2= (const float*)d_in[13];
    const float* upd_sb2= (const float*)d_in[14];
    float* out = (float*)d_out;

    float *s, *vA, *vB, *phi, *hid, *uv, *vv, *xcat, *am, *unit, *rbf, *env;
    int *ei, *ej, *deg, *pos, *startp, *sortedp;
    cudaGetSymbolAddress((void**)&s,    g_s);
    cudaGetSymbolAddress((void**)&vA,   g_vA);
    cudaGetSymbolAddress((void**)&vB,   g_vB);
    cudaGetSymbolAddress((void**)&phi,  g_phi);
    cudaGetSymbolAddress((void**)&hid,  g_hid);
    cudaGetSymbolAddress((void**)&uv,   g_uv);
    cudaGetSymbolAddress((void**)&vv,   g_vv);
    cudaGetSymbolAddress((void**)&xcat, g_xcat);
    cudaGetSymbolAddress((void**)&am,   g_am);
    cudaGetSymbolAddress((void**)&unit, g_unit);
    cudaGetSymbolAddress((void**)&rbf,  g_rbf);
    cudaGetSymbolAddress((void**)&env,  g_env);
    cudaGetSymbolAddress((void**)&ei,   g_ei);
    cudaGetSymbolAddress((void**)&ej,   g_ej);
    cudaGetSymbolAddress((void**)&deg,    g_deg);
    cudaGetSymbolAddress((void**)&pos,    g_pos);
    cudaGetSymbolAddress((void**)&startp, g_start);
    cudaGetSymbolAddress((void**)&sortedp,g_sorted);

    cudaFuncSetAttribute(mma_gemm_kernel<true>,
                         cudaFuncAttributeMaxDynamicSharedMemorySize, GEMM_SMEM_BYTES);
    cudaFuncSetAttribute(mma_gemm_kernel<false>,
                         cudaFuncAttributeMaxDynamicSharedMemorySize, GEMM_SMEM_BYTES);

    const int TPB = 256;
    // init state
    copy4_kernel<<<(NF/4 + TPB-1)/TPB, TPB>>>((float4*)s, (const float4*)cg_s, NF/4);
    zero4_kernel<<<(3*NF/4 + TPB-1)/TPB, TPB>>>((float4*)vA, 3*NF/4);
    // edge geometry + CSR build
    edge_geom_kernel<<<(EDG + TPB-1)/TPB, TPB>>>(xyz, nbr, unit, rbf, env, ei, ej);
    zeroi_kernel<<<(NN + TPB-1)/TPB, TPB>>>(deg, pos, NN);
    hist_kernel<<<(EDG + TPB-1)/TPB, TPB>>>(ei, deg);
    scan_kernel<<<1, 1024>>>(deg, startp);
    scatter_kernel<<<(EDG + TPB-1)/TPB, TPB>>>(ei, startp, pos, sortedp);

    const int RT = (NN + 127) / 128;   // 157 row tiles
    float* v_cur = vA; float* v_nxt = vB;

    for (int l = 0; l < NCONV; l++) {
        // phi = silu(s @ W1^T + b1) @ W2^T + b2
        mma_gemm_kernel<true ><<<dim3(1, RT, 1), TPB, GEMM_SMEM_BYTES>>>(
            s, 0, msg_W1 + (size_t)l*FEAT*FEAT, nullptr, msg_b1 + (size_t)l*FEAT,
            hid, nullptr, 0, NN, FEAT, FEAT);
        mma_gemm_kernel<false><<<dim3(3, RT, 1), TPB, GEMM_SMEM_BYTES>>>(
            hid, 0, msg_W2 + (size_t)l*384*FEAT, nullptr, msg_b2 + (size_t)l*384,
            phi, nullptr, 0, NN, 384, FEAT);
        // per-node gather/reduce: updates s in place, writes v_nxt = v_cur + dv
        edge_node_kernel<<<NN, 128>>>(phi, v_cur,
                                      dist_W + (size_t)l*384*NRBF, dist_b + (size_t)l*384,
                                      ej, unit, rbf, env, startp, sortedp,
                                      s, v_nxt);
        // u_v and v_v fused (shared A tile), batched over 3 spatial dims
        mma_gemm_kernel<false><<<dim3(2, RT, 3), TPB, GEMM_SMEM_BYTES>>>(
            v_nxt, (size_t)NF, upd_U + (size_t)l*FEAT*FEAT, upd_V + (size_t)l*FEAT*FEAT,
            nullptr, uv, vv, (size_t)NF, NN, FEAT, FEAT);
        // xcat = [s, ||v_v||]
        xcat_kernel<<<(NF + TPB-1)/TPB, TPB>>>(s, vv, xcat);
        // a = silu(xcat @ sW1^T + sb1) @ sW2^T + sb2
        mma_gemm_kernel<true ><<<dim3(1, RT, 1), TPB, GEMM_SMEM_BYTES>>>(
            xcat, 0, upd_sW1 + (size_t)l*FEAT*256, nullptr, upd_sb1 + (size_t)l*FEAT,
            hid, nullptr, 0, NN, FEAT, 256);
        mma_gemm_kernel<false><<<dim3(3, RT, 1), TPB, GEMM_SMEM_BYTES>>>(
            hid, 0, upd_sW2 + (size_t)l*384*FEAT, nullptr, upd_sb2 + (size_t)l*384,
            am, nullptr, 0, NN, 384, FEAT);
        // gated update (s and v_nxt in place)
        update_kernel<<<(NF + TPB-1)/TPB, TPB>>>(uv, vv, am, s, v_nxt);

        float* t = v_cur; v_cur = v_nxt; v_nxt = t;
    }

    output_kernel<<<(NF + TPB-1)/TPB, TPB>>>(s, v_cur, out);
}

// round 16
// speedup vs baseline: 1.2241x; 1.0076x over previous
#include <cuda_runtime.h>
#include <math.h>
#include <stdint.h>

// ---------------- problem constants ----------------
#define NN      20000      // nodes
#define FEAT    128
#define E0      100000     // undirected edges
#define EDG     200000     // directed (doubled)
#define NRBF    20
#define NCONV   3
#define CUTOFF  20.0f
#define PI_F    3.14159265358979323846f

#define NF      (NN*FEAT)          // 2,560,000
#define N3F     (NN*384)           // 7,680,000

// ---------------- device scratch (no cudaMalloc allowed) ----------------
__device__ float g_s [NF];
__device__ float g_vA[3*NF];
__device__ float g_vB[3*NF];
__device__ float g_phi[N3F];
__device__ float g_hid[NF];
__device__ float g_uv[3*NF];
__device__ float g_vv[3*NF];
__device__ float g_xcat[NN*256];
__device__ float g_am[N3F];
__device__ float g_unit[EDG*3];
__device__ float g_rbf[EDG*NRBF];
__device__ float g_env[EDG];
__device__ int   g_ei[EDG];
__device__ int   g_ej[EDG];
// CSR sort scratch
__device__ int   g_deg[NN];
__device__ int   g_pos[NN];
__device__ int   g_start[NN+1];
__device__ int   g_sorted[EDG];

// ---------------- helpers ----------------
__device__ __forceinline__ float tf32_rna(float x) {
    uint32_t u; asm("cvt.rna.tf32.f32 %0, %1;" : "=r"(u) : "f"(x));
    return __uint_as_float(u);
}
__device__ __forceinline__ void mma_tf32(float* c, const uint32_t* a, uint32_t b0, uint32_t b1) {
    asm volatile(
        "mma.sync.aligned.m16n8k8.row.col.f32.tf32.tf32.f32 "
        "{%0,%1,%2,%3}, {%4,%5,%6,%7}, {%8,%9}, {%0,%1,%2,%3};"
        : "+f"(c[0]), "+f"(c[1]), "+f"(c[2]), "+f"(c[3])
        : "r"(a[0]), "r"(a[1]), "r"(a[2]), "r"(a[3]), "r"(b0), "r"(b1));
}
__device__ __forceinline__ void cp16(uint32_t dst, const void* src, bool pred) {
    int sz = pred ? 16 : 0;
    asm volatile("cp.async.ca.shared.global [%0], [%1], 16, %2;"
                 :: "r"(dst), "l"(src), "r"(sz) : "memory");
}

// ---------------- small utility kernels ----------------
__global__ void copy4_kernel(float4* __restrict__ dst, const float4* __restrict__ src, int n4) {
    int i = blockIdx.x * blockDim.x + threadIdx.x;
    if (i < n4) dst[i] = src[i];
}
__global__ void zero4_kernel(float4* __restrict__ dst, int n4) {
    int i = blockIdx.x * blockDim.x + threadIdx.x;
    if (i < n4) dst[i] = make_float4(0.f,0.f,0.f,0.f);
}
__global__ void zeroi_kernel(int* __restrict__ a, int* __restrict__ b, int n) {
    int i = blockIdx.x * blockDim.x + threadIdx.x;
    if (i < n) { a[i] = 0; b[i] = 0; }
}

// ---------------- edge geometry precompute ----------------
__global__ void edge_geom_kernel(const float* __restrict__ xyz, const int* __restrict__ nbr,
                                 float* __restrict__ unit, float* __restrict__ rbf,
                                 float* __restrict__ env, int* __restrict__ ei, int* __restrict__ ej) {
    int e = blockIdx.x * blockDim.x + threadIdx.x;
    if (e >= EDG) return;
    int p = (e < E0) ? e : (e - E0);
    int a = nbr[p*2], b = nbr[p*2+1];
    int i = (e < E0) ? a : b;
    int j = (e < E0) ? b : a;
    float dx = xyz[j*3+0] - xyz[i*3+0];
    float dy = xyz[j*3+1] - xyz[i*3+1];
    float dz = xyz[j*3+2] - xyz[i*3+2];
    float d  = sqrtf(dx*dx + dy*dy + dz*dz);
    float invd = 1.0f / d;
    unit[e*3+0] = dx*invd; unit[e*3+1] = dy*invd; unit[e*3+2] = dz*invd;
    #pragma unroll
    for (int k = 0; k < NRBF; k++)
        rbf[e*NRBF + k] = sinf((float)(k+1) * PI_F * d / CUTOFF) * invd;
    env[e] = (d < CUTOFF) ? 0.5f * (cosf(PI_F * d / CUTOFF) + 1.0f) : 0.0f;
    ei[e] = i; ej[e] = j;
}

// ---------------- CSR build: histogram, scan, scatter ----------------
__global__ void hist_kernel(const int* __restrict__ ei, int* __restrict__ deg) {
    int e = blockIdx.x * blockDim.x + threadIdx.x;
    if (e < EDG) atomicAdd(&deg[ei[e]], 1);
}
__global__ void scan_kernel(const int* __restrict__ deg, int* __restrict__ start) {
    __shared__ int ssum[1024];
    const int tid = threadIdx.x;
    const int CH = (NN + 1023) / 1024;   // 20
    int base = tid * CH;
    int local = 0;
    for (int k = 0; k < CH; k++) {
        int idx = base + k;
        if (idx < NN) local += deg[idx];
    }
    ssum[tid] = local;
    __syncthreads();
    for (int off = 1; off < 1024; off <<= 1) {
        int t = (tid >= off) ? ssum[tid - off] : 0;
        __syncthreads();
        ssum[tid] += t;
        __syncthreads();
    }
    int run = ssum[tid] - local;
    for (int k = 0; k < CH; k++) {
        int idx = base + k;
        if (idx < NN) { start[idx] = run; run += deg[idx]; }
    }
    if (tid == 1023) start[NN] = ssum[1023];
}
__global__ void scatter_kernel(const int* __restrict__ ei, const int* __restrict__ start,
                               int* __restrict__ pos, int* __restrict__ sorted) {
    int e = blockIdx.x * blockDim.x + threadIdx.x;
    if (e >= EDG) return;
    int i = ei[e];
    int p = start[i] + atomicAdd(&pos[i], 1);
    sorted[p] = e;
}

// =====================================================================
// mma.sync TF32x3 GEMM, cp.async 2-stage pipeline, reg-side hi/lo split.
// K-CHUNK = 32 (pitch 36, conflict-free) — HALF the chunk iterations of
// the R10/R15 structure; per-chunk content doubled. Tests the measured
// invariance T = n_iter * C(const).
// =====================================================================
#define PITCH 36
#define NSTAGE 2
#define STAGE_F (2 * 128 * PITCH)                  // A + B planes per stage
#define GEMM_SMEM_BYTES (NSTAGE * STAGE_F * 4)     // 73,728 bytes

template<bool SILU>
__global__ void __launch_bounds__(256)
mma_gemm_kernel(const float* __restrict__ A, size_t aStride,
                const float* __restrict__ W, const float* __restrict__ W2,
                const float* __restrict__ bias,
                float* __restrict__ C, float* __restrict__ C2, size_t cStride,
                int Nrows, int Mcols, int K) {
    extern __shared__ float sm[];

    const int tid = threadIdx.x;
    const int wid = tid >> 5;
    const int lid = tid & 31;
    const int tq  = lid >> 2;
    const int tr  = lid & 3;
    const int warpRow = (wid & 3) * 32;
    const int warpCol = (wid >> 2) * 64;
    const int rowBase = blockIdx.y * 128;

    const int colTiles = (Mcols + 127) >> 7;
    int bx = blockIdx.x;
    const float* Wsel = W;
    float* Csel = C;
    if (W2 != nullptr && bx >= colTiles) { Wsel = W2; Csel = C2; bx -= colTiles; }
    const int colBase = bx * 128;

    A    += (size_t)blockIdx.z * aStride;
    Csel += (size_t)blockIdx.z * cStride;
    const float* Wt = Wsel + (size_t)colBase * K;

    const uint32_t smBase = (uint32_t)__cvta_generic_to_shared(sm);

    const int ldRow0 = tid >> 2;        // 0..63
    const int ldQ    = (tid & 3) * 8;   // 0,8,16,24

    float acc[2][8][4];
    #pragma unroll
    for (int mf = 0; mf < 2; mf++)
        #pragma unroll
        for (int nf = 0; nf < 8; nf++)
            #pragma unroll
            for (int u = 0; u < 4; u++) acc[mf][nf][u] = 0.f;

    const int nch = K >> 5;             // chunks of 32

    auto issue_stage = [&](int c, int buf) {
        const int k0 = c * 32;
        uint32_t aSm = smBase + (uint32_t)(buf * STAGE_F) * 4u;
        uint32_t bSm = aSm + (uint32_t)(128 * PITCH) * 4u;
        #pragma unroll
        for (int half = 0; half < 2; half++) {
            int row = half * 64 + ldRow0;
            int r = rowBase + row;
            uint32_t soff = (uint32_t)(row * PITCH + ldQ) * 4u;
            cp16(aSm + soff,      &A[(size_t)r * K + k0 + ldQ],     r < Nrows);
            cp16(aSm + soff + 16, &A[(size_t)r * K + k0 + ldQ + 4], r < Nrows);
            cp16(bSm + soff,      &Wt[(size_t)row * K + k0 + ldQ],     true);
            cp16(bSm + soff + 16, &Wt[(size_t)row * K + k0 + ldQ + 4], true);
        }
        asm volatile("cp.async.commit_group;" ::: "memory");
    };

    issue_stage(0, 0);

    for (int c = 0; c < nch; c++) {
        if (c + 1 < nch) {
            issue_stage(c + 1, (c + 1) & 1);
            asm volatile("cp.async.wait_group 1;" ::: "memory");
        } else {
            asm volatile("cp.async.wait_group 0;" ::: "memory");
        }
        __syncthreads();

        const float* Ab = sm + (c & 1) * STAGE_F;
        const float* Bb = Ab + 128 * PITCH;

        #pragma unroll
        for (int ks = 0; ks < 4; ks++) {
            const int kc = ks * 8;
            uint32_t ah[2][4], al[2][4];
            #pragma unroll
            for (int mf = 0; mf < 2; mf++) {
                int r0 = warpRow + mf * 16 + tq;
                float a0 = Ab[(r0    ) * PITCH + kc + tr    ];
                float a1 = Ab[(r0 + 8) * PITCH + kc + tr    ];
                float a2 = Ab[(r0    ) * PITCH + kc + tr + 4];
                float a3 = Ab[(r0 + 8) * PITCH + kc + tr + 4];
                float h0 = tf32_rna(a0), h1 = tf32_rna(a1), h2 = tf32_rna(a2), h3 = tf32_rna(a3);
                ah[mf][0] = __float_as_uint(h0); al[mf][0] = __float_as_uint(a0 - h0);
                ah[mf][1] = __float_as_uint(h1); al[mf][1] = __float_as_uint(a1 - h1);
                ah[mf][2] = __float_as_uint(h2); al[mf][2] = __float_as_uint(a2 - h2);
                ah[mf][3] = __float_as_uint(h3); al[mf][3] = __float_as_uint(a3 - h3);
            }
            #pragma unroll
            for (int nf = 0; nf < 8; nf++) {
                int c0 = warpCol + nf * 8 + tq;
                float b0 = Bb[c0 * PITCH + kc + tr    ];
                float b1 = Bb[c0 * PITCH + kc + tr + 4];
                float bh0f = tf32_rna(b0), bh1f = tf32_rna(b1);
                uint32_t bh0 = __float_as_uint(bh0f);
                uint32_t bh1 = __float_as_uint(bh1f);
                uint32_t bl0 = __float_as_uint(b0 - bh0f);
                uint32_t bl1 = __float_as_uint(b1 - bh1f);
                #pragma unroll
                for (int mf = 0; mf < 2; mf++) {
                    mma_tf32(acc[mf][nf], ah[mf], bh0, bh1);
                    mma_tf32(acc[mf][nf], al[mf], bh0, bh1);
                    mma_tf32(acc[mf][nf], ah[mf], bl0, bl1);
                }
            }
        }
        __syncthreads();
    }

    #pragma unroll
    for (int mf = 0; mf < 2; mf++) {
        int r0 = rowBase + warpRow + mf * 16 + tq;
        #pragma unroll
        for (int nf = 0; nf < 8; nf++) {
            int cb = colBase + warpCol + nf * 8 + tr * 2;
            float b0 = bias ? bias[cb] : 0.f;
            float b1 = bias ? bias[cb + 1] : 0.f;
            float v0 = acc[mf][nf][0] + b0;
            float v1 = acc[mf][nf][1] + b1;
            float v2 = acc[mf][nf][2] + b0;
            float v3 = acc[mf][nf][3] + b1;
            if (SILU) {
                v0 = v0 / (1.f + expf(-v0));
                v1 = v1 / (1.f + expf(-v1));
                v2 = v2 / (1.f + expf(-v2));
                v3 = v3 / (1.f + expf(-v3));
            }
            if (r0 < Nrows)      *(float2*)&Csel[(size_t)r0      * Mcols + cb] = make_float2(v0, v1);
            if (r0 + 8 < Nrows)  *(float2*)&Csel[(size_t)(r0 + 8) * Mcols + cb] = make_float2(v2, v3);
        }
    }
}

// ---------------- per-node edge gather (R10 winner — one CTA per node) ----------------
__global__ void __launch_bounds__(128)
edge_node_kernel(const float* __restrict__ phi,
                 const float* __restrict__ v_old,
                 const float* __restrict__ distW,
                 const float* __restrict__ distb,
                 const int* __restrict__ ej,
                 const float* __restrict__ unit, const float* __restrict__ rbf,
                 const float* __restrict__ env,
                 const int* __restrict__ start, const int* __restrict__ sorted,
                 float* __restrict__ s, float* __restrict__ v_new) {
    const int n = blockIdx.x;
    const int f = threadIdx.x;

    float w[3][NRBF];
    float bch[3];
    #pragma unroll
    for (int c = 0; c < 3; c++) {
        const float4* src = (const float4*)&distW[(c * 128 + f) * NRBF];
        #pragma unroll
        for (int q = 0; q < 5; q++) {
            float4 v4 = src[q];
            w[c][q*4+0] = v4.x; w[c][q*4+1] = v4.y; w[c][q*4+2] = v4.z; w[c][q*4+3] = v4.w;
        }
        bch[c] = distb[c * 128 + f];
    }

    const size_t nb = (size_t)n * 128 + f;
    float sAcc = s[nb];
    float a0 = v_old[nb];
    float a1 = v_old[NF + nb];
    float a2 = v_old[2*NF + nb];

    const int e0 = start[n], e1 = start[n + 1];
    for (int k = e0; k < e1; k++) {
        int e = sorted[k];
        int j = ej[e];
        float rb[NRBF];
        {
            const float4* src = (const float4*)&rbf[e * NRBF];
            #pragma unroll
            for (int q = 0; q < 5; q++) {
                float4 v4 = src[q];
                rb[q*4+0] = v4.x; rb[q*4+1] = v4.y; rb[q*4+2] = v4.z; rb[q*4+3] = v4.w;
            }
        }
        float ev = env[e];
        float u0 = unit[e*3+0], u1 = unit[e*3+1], u2 = unit[e*3+2];

        const float* phij = phi + (size_t)j * 384 + f;
        float inv[3];
        #pragma unroll
        for (int c = 0; c < 3; c++) {
            float acc = bch[c];
            #pragma unroll
            for (int kk = 0; kk < NRBF; kk++) acc += rb[kk] * w[c][kk];
            inv[c] = phij[c * 128] * (acc * ev);
        }

        const size_t jb = (size_t)j * 128 + f;
        sAcc += inv[1];
        a0 += inv[2]*u0 + inv[0]*v_old[jb];
        a1 += inv[2]*u1 + inv[0]*v_old[NF + jb];
        a2 += inv[2]*u2 + inv[0]*v_old[2*NF + jb];
    }

    s[nb] = sAcc;
    v_new[nb]        = a0;
    v_new[NF + nb]   = a1;
    v_new[2*NF + nb] = a2;
}

// ---------------- xcat = [s, ||v_v||] ----------------
__global__ void xcat_kernel(const float* __restrict__ s, const float* __restrict__ vv,
                            float* __restrict__ xcat) {
    int idx = blockIdx.x * blockDim.x + threadIdx.x;
    if (idx >= NF) return;
    int n = idx >> 7, f = idx & 127;
    float a = vv[idx], b = vv[NF + idx], c = vv[2*NF + idx];
    xcat[(size_t)n*256 + f]       = s[idx];
    xcat[(size_t)n*256 + 128 + f] = sqrtf(a*a + b*b + c*c);
}

// ---------------- final gated update (in place) ----------------
__global__ void update_kernel(const float* __restrict__ uv, const float* __restrict__ vv,
                              const float* __restrict__ am,
                              float* __restrict__ s, float* __restrict__ v) {
    int idx = blockIdx.x * blockDim.x + threadIdx.x;
    if (idx >= NF) return;
    int n = idx >> 7, f = idx & 127;
    float dot = uv[idx]*vv[idx] + uv[NF+idx]*vv[NF+idx] + uv[2*NF+idx]*vv[2*NF+idx];
    float a0 = am[(size_t)n*384 + f];
    float a1 = am[(size_t)n*384 + 128 + f];
    float a2 = am[(size_t)n*384 + 256 + f];
    s[idx] += dot * a1 + a2;
    #pragma unroll
    for (int d = 0; d < 3; d++)
        v[(size_t)d*NF + idx] += uv[(size_t)d*NF + idx] * a0;
}

// ---------------- pack output: s flat, then v as (N,128,3) ----------------
__global__ void output_kernel(const float* __restrict__ s, const float* __restrict__ v,
                              float* __restrict__ out) {
    int idx = blockIdx.x * blockDim.x + threadIdx.x;
    if (idx >= NF) return;
    int n = idx >> 7, f = idx & 127;
    out[idx] = s[idx];
    #pragma unroll
    for (int d = 0; d < 3; d++)
        out[(size_t)NF + (size_t)n*384 + f*3 + d] = v[(size_t)d*NF + idx];
}

// ---------------- host orchestration ----------------
extern "C" void kernel_launch(void* const* d_in, const int* in_sizes, int n_in,
                              void* d_out, int out_size) {
    const float* xyz    = (const float*)d_in[0];
    const int*   nbr    = (const int*)  d_in[1];
    const float* cg_s   = (const float*)d_in[2];
    const float* msg_W1 = (const float*)d_in[3];
    const float* msg_b1 = (const float*)d_in[4];
    const float* msg_W2 = (const float*)d_in[5];
    const float* msg_b2 = (const float*)d_in[6];
    const float* dist_W = (const float*)d_in[7];
    const float* dist_b = (const float*)d_in[8];
    const float* upd_U  = (const float*)d_in[9];
    const float* upd_V  = (const float*)d_in[10];
    const float* upd_sW1= (const float*)d_in[11];
    const float* upd_sb1= (const float*)d_in[12];
    const float* upd_sW2= (const float*)d_in[13];
    const float* upd_sb2= (const float*)d_in[14];
    float* out = (float*)d_out;

    float *s, *vA, *vB, *phi, *hid, *uv, *vv, *xcat, *am, *unit, *rbf, *env;
    int *ei, *ej, *deg, *pos, *startp, *sortedp;
    cudaGetSymbolAddress((void**)&s,    g_s);
    cudaGetSymbolAddress((void**)&vA,   g_vA);
    cudaGetSymbolAddress((void**)&vB,   g_vB);
    cudaGetSymbolAddress((void**)&phi,  g_phi);
    cudaGetSymbolAddress((void**)&hid,  g_hid);
    cudaGetSymbolAddress((void**)&uv,   g_uv);
    cudaGetSymbolAddress((void**)&vv,   g_vv);
    cudaGetSymbolAddress((void**)&xcat, g_xcat);
    cudaGetSymbolAddress((void**)&am,   g_am);
    cudaGetSymbolAddress((void**)&unit, g_unit);
    cudaGetSymbolAddress((void**)&rbf,  g_rbf);
    cudaGetSymbolAddress((void**)&env,  g_env);
    cudaGetSymbolAddress((void**)&ei,   g_ei);
    cudaGetSymbolAddress((void**)&ej,   g_ej);
    cudaGetSymbolAddress((void**)&deg,    g_deg);
    cudaGetSymbolAddress((void**)&pos,    g_pos);
    cudaGetSymbolAddress((void**)&startp, g_start);
    cudaGetSymbolAddress((void**)&sortedp,g_sorted);

    cudaFuncSetAttribute(mma_gemm_kernel<true>,
                         cudaFuncAttributeMaxDynamicSharedMemorySize, GEMM_SMEM_BYTES);
    cudaFuncSetAttribute(mma_gemm_kernel<false>,
                         cudaFuncAttributeMaxDynamicSharedMemorySize, GEMM_SMEM_BYTES);

    const int TPB = 256;
    // init state
    copy4_kernel<<<(NF/4 + TPB-1)/TPB, TPB>>>((float4*)s, (const float4*)cg_s, NF/4);
    zero4_kernel<<<(3*NF/4 + TPB-1)/TPB, TPB>>>((float4*)vA, 3*NF/4);
    // edge geometry + CSR build
    edge_geom_kernel<<<(EDG + TPB-1)/TPB, TPB>>>(xyz, nbr, unit, rbf, env, ei, ej);
    zeroi_kernel<<<(NN + TPB-1)/TPB, TPB>>>(deg, pos, NN);
    hist_kernel<<<(EDG + TPB-1)/TPB, TPB>>>(ei, deg);
    scan_kernel<<<1, 1024>>>(deg, startp);
    scatter_kernel<<<(EDG + TPB-1)/TPB, TPB>>>(ei, startp, pos, sortedp);

    const int RT = (NN + 127) / 128;   // 157 row tiles
    float* v_cur = vA; float* v_nxt = vB;

    for (int l = 0; l < NCONV; l++) {
        // phi = silu(s @ W1^T + b1) @ W2^T + b2
        mma_gemm_kernel<true ><<<dim3(1, RT, 1), TPB, GEMM_SMEM_BYTES>>>(
            s, 0, msg_W1 + (size_t)l*FEAT*FEAT, nullptr, msg_b1 + (size_t)l*FEAT,
            hid, nullptr, 0, NN, FEAT, FEAT);
        mma_gemm_kernel<false><<<dim3(3, RT, 1), TPB, GEMM_SMEM_BYTES>>>(
            hid, 0, msg_W2 + (size_t)l*384*FEAT, nullptr, msg_b2 + (size_t)l*384,
            phi, nullptr, 0, NN, 384, FEAT);
        // per-node gather/reduce: updates s in place, writes v_nxt = v_cur + dv
        edge_node_kernel<<<NN, 128>>>(phi, v_cur,
                                      dist_W + (size_t)l*384*NRBF, dist_b + (size_t)l*384,
                                      ej, unit, rbf, env, startp, sortedp,
                                      s, v_nxt);
        // u_v and v_v fused (shared A tile), batched over 3 spatial dims
        mma_gemm_kernel<false><<<dim3(2, RT, 3), TPB, GEMM_SMEM_BYTES>>>(
            v_nxt, (size_t)NF, upd_U + (size_t)l*FEAT*FEAT, upd_V + (size_t)l*FEAT*FEAT,
            nullptr, uv, vv, (size_t)NF, NN, FEAT, FEAT);
        // xcat = [s, ||v_v||]
        xcat_kernel<<<(NF + TPB-1)/TPB, TPB>>>(s, vv, xcat);
        // a = silu(xcat @ sW1^T + sb1) @ sW2^T + sb2
        mma_gemm_kernel<true ><<<dim3(1, RT, 1), TPB, GEMM_SMEM_BYTES>>>(
            xcat, 0, upd_sW1 + (size_t)l*FEAT*256, nullptr, upd_sb1 + (size_t)l*FEAT,
            hid, nullptr, 0, NN, FEAT, 256);
        mma_gemm_kernel<false><<<dim3(3, RT, 1), TPB, GEMM_SMEM_BYTES>>>(
            hid, 0, upd_sW2 + (size_t)l*384*FEAT, nullptr, upd_sb2 + (size_t)l*384,
            am, nullptr, 0, NN, 384, FEAT);
        // gated update (s and v_nxt in place)
        update_kernel<<<(NF + TPB-1)/TPB, TPB>>>(uv, vv, am, s, v_nxt);

        float* t = v_cur; v_cur = v_nxt; v_nxt = t;
    }

    output_kernel<<<(NF + TPB-1)/TPB, TPB>>>(s, v_cur, out);
}

// round 17
// speedup vs baseline: 1.2468x; 1.0186x over previous
#include <cuda_runtime.h>
#include <math.h>
#include <stdint.h>

// ---------------- problem constants ----------------
#define NN      20000      // nodes
#define FEAT    128
#define E0      100000     // undirected edges
#define EDG     200000     // directed (doubled)
#define NRBF    20
#define NCONV   3
#define CUTOFF  20.0f
#define PI_F    3.14159265358979323846f

#define NF      (NN*FEAT)          // 2,560,000
#define N3F     (NN*384)           // 7,680,000

// ---------------- device scratch (no cudaMalloc allowed) ----------------
__device__ float g_s [NF];
__device__ float g_vA[3*NF];
__device__ float g_vB[3*NF];
__device__ float g_phi[N3F];
__device__ float g_hid[NF];
__device__ float g_uv[3*NF];
__device__ float g_vv[3*NF];
__device__ float g_xcat[NN*256];
__device__ float g_am[N3F];
__device__ float g_unit[EDG*3];
__device__ float g_rbf[EDG*NRBF];
__device__ float g_env[EDG];
__device__ int   g_ei[EDG];
__device__ int   g_ej[EDG];
// CSR sort scratch
__device__ int   g_deg[NN];
__device__ int   g_pos[NN];
__device__ int   g_start[NN+1];
__device__ int   g_sorted[EDG];

// ---------------- helpers ----------------
__device__ __forceinline__ float tf32_rna(float x) {
    uint32_t u; asm("cvt.rna.tf32.f32 %0, %1;" : "=r"(u) : "f"(x));
    return __uint_as_float(u);
}
__device__ __forceinline__ void mma_tf32(float* c, const uint32_t* a, uint32_t b0, uint32_t b1) {
    asm volatile(
        "mma.sync.aligned.m16n8k8.row.col.f32.tf32.tf32.f32 "
        "{%0,%1,%2,%3}, {%4,%5,%6,%7}, {%8,%9}, {%0,%1,%2,%3};"
        : "+f"(c[0]), "+f"(c[1]), "+f"(c[2]), "+f"(c[3])
        : "r"(a[0]), "r"(a[1]), "r"(a[2]), "r"(a[3]), "r"(b0), "r"(b1));
}
__device__ __forceinline__ void cp16(uint32_t dst, const void* src, bool pred) {
    int sz = pred ? 16 : 0;
    asm volatile("cp.async.ca.shared.global [%0], [%1], 16, %2;"
                 :: "r"(dst), "l"(src), "r"(sz) : "memory");
}
__device__ __forceinline__ float silu_fast(float v) {
    return v / (1.f + __expf(-v));
}

// ---------------- small utility kernels ----------------
__global__ void copy4_kernel(float4* __restrict__ dst, const float4* __restrict__ src, int n4) {
    int i = blockIdx.x * blockDim.x + threadIdx.x;
    if (i < n4) dst[i] = src[i];
}
__global__ void zero4_kernel(float4* __restrict__ dst, int n4) {
    int i = blockIdx.x * blockDim.x + threadIdx.x;
    if (i < n4) dst[i] = make_float4(0.f,0.f,0.f,0.f);
}
__global__ void zeroi_kernel(int* __restrict__ a, int* __restrict__ b, int n) {
    int i = blockIdx.x * blockDim.x + threadIdx.x;
    if (i < n) { a[i] = 0; b[i] = 0; }
}

// ---------------- edge geometry precompute ----------------
// sin(k*theta) via Chebyshev recurrence: 1 __sincosf instead of 20 sinf.
__global__ void edge_geom_kernel(const float* __restrict__ xyz, const int* __restrict__ nbr,
                                 float* __restrict__ unit, float* __restrict__ rbf,
                                 float* __restrict__ env, int* __restrict__ ei, int* __restrict__ ej) {
    int e = blockIdx.x * blockDim.x + threadIdx.x;
    if (e >= EDG) return;
    int p = (e < E0) ? e : (e - E0);
    int a = nbr[p*2], b = nbr[p*2+1];
    int i = (e < E0) ? a : b;
    int j = (e < E0) ? b : a;
    float dx = xyz[j*3+0] - xyz[i*3+0];
    float dy = xyz[j*3+1] - xyz[i*3+1];
    float dz = xyz[j*3+2] - xyz[i*3+2];
    float d  = sqrtf(dx*dx + dy*dy + dz*dz);
    float invd = 1.0f / d;
    unit[e*3+0] = dx*invd; unit[e*3+1] = dy*invd; unit[e*3+2] = dz*invd;

    float theta = PI_F * d / CUTOFF;     // <= ~2.8 rad for this box
    float s1, c1;
    __sincosf(theta, &s1, &c1);
    float twoc = 2.0f * c1;
    float skm1 = 0.0f;                    // sin(0)
    float sk   = s1;                      // sin(theta)
    rbf[e*NRBF + 0] = sk * invd;
    #pragma unroll
    for (int k = 1; k < NRBF; k++) {
        float skp1 = twoc * sk - skm1;    // sin((k+1)theta)
        skm1 = sk; sk = skp1;
        rbf[e*NRBF + k] = sk * invd;
    }
    env[e] = (d < CUTOFF) ? 0.5f * (c1 + 1.0f) : 0.0f;
    ei[e] = i; ej[e] = j;
}

// ---------------- CSR build: histogram, scan, scatter ----------------
__global__ void hist_kernel(const int* __restrict__ ei, int* __restrict__ deg) {
    int e = blockIdx.x * blockDim.x + threadIdx.x;
    if (e < EDG) atomicAdd(&deg[ei[e]], 1);
}
__global__ void scan_kernel(const int* __restrict__ deg, int* __restrict__ start) {
    __shared__ int ssum[1024];
    const int tid = threadIdx.x;
    const int CH = (NN + 1023) / 1024;   // 20
    int base = tid * CH;
    int local = 0;
    for (int k = 0; k < CH; k++) {
        int idx = base + k;
        if (idx < NN) local += deg[idx];
    }
    ssum[tid] = local;
    __syncthreads();
    for (int off = 1; off < 1024; off <<= 1) {
        int t = (tid >= off) ? ssum[tid - off] : 0;
        __syncthreads();
        ssum[tid] += t;
        __syncthreads();
    }
    int run = ssum[tid] - local;
    for (int k = 0; k < CH; k++) {
        int idx = base + k;
        if (idx < NN) { start[idx] = run; run += deg[idx]; }
    }
    if (tid == 1023) start[NN] = ssum[1023];
}
__global__ void scatter_kernel(const int* __restrict__ ei, const int* __restrict__ start,
                               int* __restrict__ pos, int* __restrict__ sorted) {
    int e = blockIdx.x * blockDim.x + threadIdx.x;
    if (e >= EDG) return;
    int i = ei[e];
    int p = start[i] + atomicAdd(&pos[i], 1);
    sorted[p] = e;
}

// =====================================================================
// mma.sync TF32x3 GEMM, cp.async 2-stage pipeline, K-chunk 32 (R16 winner).
// =====================================================================
#define PITCH 36
#define NSTAGE 2
#define STAGE_F (2 * 128 * PITCH)                  // A + B planes per stage
#define GEMM_SMEM_BYTES (NSTAGE * STAGE_F * 4)     // 73,728 bytes

template<bool SILU>
__global__ void __launch_bounds__(256)
mma_gemm_kernel(const float* __restrict__ A, size_t aStride,
                const float* __restrict__ W, const float* __restrict__ W2,
                const float* __restrict__ bias,
                float* __restrict__ C, float* __restrict__ C2, size_t cStride,
                int Nrows, int Mcols, int K) {
    extern __shared__ float sm[];

    const int tid = threadIdx.x;
    const int wid = tid >> 5;
    const int lid = tid & 31;
    const int tq  = lid >> 2;
    const int tr  = lid & 3;
    const int warpRow = (wid & 3) * 32;
    const int warpCol = (wid >> 2) * 64;
    const int rowBase = blockIdx.y * 128;

    const int colTiles = (Mcols + 127) >> 7;
    int bx = blockIdx.x;
    const float* Wsel = W;
    float* Csel = C;
    if (W2 != nullptr && bx >= colTiles) { Wsel = W2; Csel = C2; bx -= colTiles; }
    const int colBase = bx * 128;

    A    += (size_t)blockIdx.z * aStride;
    Csel += (size_t)blockIdx.z * cStride;
    const float* Wt = Wsel + (size_t)colBase * K;

    const uint32_t smBase = (uint32_t)__cvta_generic_to_shared(sm);

    const int ldRow0 = tid >> 2;        // 0..63
    const int ldQ    = (tid & 3) * 8;   // 0,8,16,24

    float acc[2][8][4];
    #pragma unroll
    for (int mf = 0; mf < 2; mf++)
        #pragma unroll
        for (int nf = 0; nf < 8; nf++)
            #pragma unroll
            for (int u = 0; u < 4; u++) acc[mf][nf][u] = 0.f;

    const int nch = K >> 5;             // chunks of 32

    auto issue_stage = [&](int c, int buf) {
        const int k0 = c * 32;
        uint32_t aSm = smBase + (uint32_t)(buf * STAGE_F) * 4u;
        uint32_t bSm = aSm + (uint32_t)(128 * PITCH) * 4u;
        #pragma unroll
        for (int half = 0; half < 2; half++) {
            int row = half * 64 + ldRow0;
            int r = rowBase + row;
            uint32_t soff = (uint32_t)(row * PITCH + ldQ) * 4u;
            cp16(aSm + soff,      &A[(size_t)r * K + k0 + ldQ],     r < Nrows);
            cp16(aSm + soff + 16, &A[(size_t)r * K + k0 + ldQ + 4], r < Nrows);
            cp16(bSm + soff,      &Wt[(size_t)row * K + k0 + ldQ],     true);
            cp16(bSm + soff + 16, &Wt[(size_t)row * K + k0 + ldQ + 4], true);
        }
        asm volatile("cp.async.commit_group;" ::: "memory");
    };

    issue_stage(0, 0);

    for (int c = 0; c < nch; c++) {
        if (c + 1 < nch) {
            issue_stage(c + 1, (c + 1) & 1);
            asm volatile("cp.async.wait_group 1;" ::: "memory");
        } else {
            asm volatile("cp.async.wait_group 0;" ::: "memory");
        }
        __syncthreads();

        const float* Ab = sm + (c & 1) * STAGE_F;
        const float* Bb = Ab + 128 * PITCH;

        #pragma unroll
        for (int ks = 0; ks < 4; ks++) {
            const int kc = ks * 8;
            uint32_t ah[2][4], al[2][4];
            #pragma unroll
            for (int mf = 0; mf < 2; mf++) {
                int r0 = warpRow + mf * 16 + tq;
                float a0 = Ab[(r0    ) * PITCH + kc + tr    ];
                float a1 = Ab[(r0 + 8) * PITCH + kc + tr    ];
                float a2 = Ab[(r0    ) * PITCH + kc + tr + 4];
                float a3 = Ab[(r0 + 8) * PITCH + kc + tr + 4];
                float h0 = tf32_rna(a0), h1 = tf32_rna(a1), h2 = tf32_rna(a2), h3 = tf32_rna(a3);
                ah[mf][0] = __float_as_uint(h0); al[mf][0] = __float_as_uint(a0 - h0);
                ah[mf][1] = __float_as_uint(h1); al[mf][1] = __float_as_uint(a1 - h1);
                ah[mf][2] = __float_as_uint(h2); al[mf][2] = __float_as_uint(a2 - h2);
                ah[mf][3] = __float_as_uint(h3); al[mf][3] = __float_as_uint(a3 - h3);
            }
            #pragma unroll
            for (int nf = 0; nf < 8; nf++) {
                int c0 = warpCol + nf * 8 + tq;
                float b0 = Bb[c0 * PITCH + kc + tr    ];
                float b1 = Bb[c0 * PITCH + kc + tr + 4];
                float bh0f = tf32_rna(b0), bh1f = tf32_rna(b1);
                uint32_t bh0 = __float_as_uint(bh0f);
                uint32_t bh1 = __float_as_uint(bh1f);
                uint32_t bl0 = __float_as_uint(b0 - bh0f);
                uint32_t bl1 = __float_as_uint(b1 - bh1f);
                #pragma unroll
                for (int mf = 0; mf < 2; mf++) {
                    mma_tf32(acc[mf][nf], ah[mf], bh0, bh1);
                    mma_tf32(acc[mf][nf], al[mf], bh0, bh1);
                    mma_tf32(acc[mf][nf], ah[mf], bl0, bl1);
                }
            }
        }
        __syncthreads();
    }

    #pragma unroll
    for (int mf = 0; mf < 2; mf++) {
        int r0 = rowBase + warpRow + mf * 16 + tq;
        #pragma unroll
        for (int nf = 0; nf < 8; nf++) {
            int cb = colBase + warpCol + nf * 8 + tr * 2;
            float b0 = bias ? bias[cb] : 0.f;
            float b1 = bias ? bias[cb + 1] : 0.f;
            float v0 = acc[mf][nf][0] + b0;
            float v1 = acc[mf][nf][1] + b1;
            float v2 = acc[mf][nf][2] + b0;
            float v3 = acc[mf][nf][3] + b1;
            if (SILU) {
                v0 = silu_fast(v0);
                v1 = silu_fast(v1);
                v2 = silu_fast(v2);
                v3 = silu_fast(v3);
            }
            if (r0 < Nrows)      *(float2*)&Csel[(size_t)r0      * Mcols + cb] = make_float2(v0, v1);
            if (r0 + 8 < Nrows)  *(float2*)&Csel[(size_t)(r0 + 8) * Mcols + cb] = make_float2(v2, v3);
        }
    }
}

// ---------------- per-node edge gather (R10 winner — one CTA per node) ----------------
__global__ void __launch_bounds__(128)
edge_node_kernel(const float* __restrict__ phi,
                 const float* __restrict__ v_old,
                 const float* __restrict__ distW,
                 const float* __restrict__ distb,
                 const int* __restrict__ ej,
                 const float* __restrict__ unit, const float* __restrict__ rbf,
                 const float* __restrict__ env,
                 const int* __restrict__ start, const int* __restrict__ sorted,
                 float* __restrict__ s, float* __restrict__ v_new) {
    const int n = blockIdx.x;
    const int f = threadIdx.x;

    float w[3][NRBF];
    float bch[3];
    #pragma unroll
    for (int c = 0; c < 3; c++) {
        const float4* src = (const float4*)&distW[(c * 128 + f) * NRBF];
        #pragma unroll
        for (int q = 0; q < 5; q++) {
            float4 v4 = src[q];
            w[c][q*4+0] = v4.x; w[c][q*4+1] = v4.y; w[c][q*4+2] = v4.z; w[c][q*4+3] = v4.w;
        }
        bch[c] = distb[c * 128 + f];
    }

    const size_t nb = (size_t)n * 128 + f;
    float sAcc = s[nb];
    float a0 = v_old[nb];
    float a1 = v_old[NF + nb];
    float a2 = v_old[2*NF + nb];

    const int e0 = start[n], e1 = start[n + 1];
    for (int k = e0; k < e1; k++) {
        int e = sorted[k];
        int j = ej[e];
        float rb[NRBF];
        {
            const float4* src = (const float4*)&rbf[e * NRBF];
            #pragma unroll
            for (int q = 0; q < 5; q++) {
                float4 v4 = src[q];
                rb[q*4+0] = v4.x; rb[q*4+1] = v4.y; rb[q*4+2] = v4.z; rb[q*4+3] = v4.w;
            }
        }
        float ev = env[e];
        float u0 = unit[e*3+0], u1 = unit[e*3+1], u2 = unit[e*3+2];

        const float* phij = phi + (size_t)j * 384 + f;
        float inv[3];
        #pragma unroll
        for (int c = 0; c < 3; c++) {
            float acc = bch[c];
            #pragma unroll
            for (int kk = 0; kk < NRBF; kk++) acc += rb[kk] * w[c][kk];
            inv[c] = phij[c * 128] * (acc * ev);
        }

        const size_t jb = (size_t)j * 128 + f;
        sAcc += inv[1];
        a0 += inv[2]*u0 + inv[0]*v_old[jb];
        a1 += inv[2]*u1 + inv[0]*v_old[NF + jb];
        a2 += inv[2]*u2 + inv[0]*v_old[2*NF + jb];
    }

    s[nb] = sAcc;
    v_new[nb]        = a0;
    v_new[NF + nb]   = a1;
    v_new[2*NF + nb] = a2;
}

// ---------------- xcat = [s, ||v_v||] ----------------
__global__ void xcat_kernel(const float* __restrict__ s, const float* __restrict__ vv,
                            float* __restrict__ xcat) {
    int idx = blockIdx.x * blockDim.x + threadIdx.x;
    if (idx >= NF) return;
    int n = idx >> 7, f = idx & 127;
    float a = vv[idx], b = vv[NF + idx], c = vv[2*NF + idx];
    xcat[(size_t)n*256 + f]       = s[idx];
    xcat[(size_t)n*256 + 128 + f] = sqrtf(a*a + b*b + c*c);
}

// ---------------- final gated update (in place) ----------------
__global__ void update_kernel(const float* __restrict__ uv, const float* __restrict__ vv,
                              const float* __restrict__ am,
                              float* __restrict__ s, float* __restrict__ v) {
    int idx = blockIdx.x * blockDim.x + threadIdx.x;
    if (idx >= NF) return;
    int n = idx >> 7, f = idx & 127;
    float dot = uv[idx]*vv[idx] + uv[NF+idx]*vv[NF+idx] + uv[2*NF+idx]*vv[2*NF+idx];
    float a0 = am[(size_t)n*384 + f];
    float a1 = am[(size_t)n*384 + 128 + f];
    float a2 = am[(size_t)n*384 + 256 + f];
    s[idx] += dot * a1 + a2;
    #pragma unroll
    for (int d = 0; d < 3; d++)
        v[(size_t)d*NF + idx] += uv[(size_t)d*NF + idx] * a0;
}

// ---------------- pack output: s flat, then v as (N,128,3) ----------------
__global__ void output_kernel(const float* __restrict__ s, const float* __restrict__ v,
                              float* __restrict__ out) {
    int idx = blockIdx.x * blockDim.x + threadIdx.x;
    if (idx >= NF) return;
    int n = idx >> 7, f = idx & 127;
    out[idx] = s[idx];
    #pragma unroll
    for (int d = 0; d < 3; d++)
        out[(size_t)NF + (size_t)n*384 + f*3 + d] = v[(size_t)d*NF + idx];
}

// ---------------- host orchestration ----------------
extern "C" void kernel_launch(void* const* d_in, const int* in_sizes, int n_in,
                              void* d_out, int out_size) {
    const float* xyz    = (const float*)d_in[0];
    const int*   nbr    = (const int*)  d_in[1];
    const float* cg_s   = (const float*)d_in[2];
    const float* msg_W1 = (const float*)d_in[3];
    const float* msg_b1 = (const float*)d_in[4];
    const float* msg_W2 = (const float*)d_in[5];
    const float* msg_b2 = (const float*)d_in[6];
    const float* dist_W = (const float*)d_in[7];
    const float* dist_b = (const float*)d_in[8];
    const float* upd_U  = (const float*)d_in[9];
    const float* upd_V  = (const float*)d_in[10];
    const float* upd_sW1= (const float*)d_in[11];
    const float* upd_sb1= (const float*)d_in[12];
    const float* upd_sW2= (const float*)d_in[13];
    const float* upd_sb2= (const float*)d_in[14];
    float* out = (float*)d_out;

    float *s, *vA, *vB, *phi, *hid, *uv, *vv, *xcat, *am, *unit, *rbf, *env;
    int *ei, *ej, *deg, *pos, *startp, *sortedp;
    cudaGetSymbolAddress((void**)&s,    g_s);
    cudaGetSymbolAddress((void**)&vA,   g_vA);
    cudaGetSymbolAddress((void**)&vB,   g_vB);
    cudaGetSymbolAddress((void**)&phi,  g_phi);
    cudaGetSymbolAddress((void**)&hid,  g_hid);
    cudaGetSymbolAddress((void**)&uv,   g_uv);
    cudaGetSymbolAddress((void**)&vv,   g_vv);
    cudaGetSymbolAddress((void**)&xcat, g_xcat);
    cudaGetSymbolAddress((void**)&am,   g_am);
    cudaGetSymbolAddress((void**)&unit, g_unit);
    cudaGetSymbolAddress((void**)&rbf,  g_rbf);
    cudaGetSymbolAddress((void**)&env,  g_env);
    cudaGetSymbolAddress((void**)&ei,   g_ei);
    cudaGetSymbolAddress((void**)&ej,   g_ej);
    cudaGetSymbolAddress((void**)&deg,    g_deg);
    cudaGetSymbolAddress((void**)&pos,    g_pos);
    cudaGetSymbolAddress((void**)&startp, g_start);
    cudaGetSymbolAddress((void**)&sortedp,g_sorted);

    cudaFuncSetAttribute(mma_gemm_kernel<true>,
                         cudaFuncAttributeMaxDynamicSharedMemorySize, GEMM_SMEM_BYTES);
    cudaFuncSetAttribute(mma_gemm_kernel<false>,
                         cudaFuncAttributeMaxDynamicSharedMemorySize, GEMM_SMEM_BYTES);

    const int TPB = 256;
    // init state
    copy4_kernel<<<(NF/4 + TPB-1)/TPB, TPB>>>((float4*)s, (const float4*)cg_s, NF/4);
    zero4_kernel<<<(3*NF/4 + TPB-1)/TPB, TPB>>>((float4*)vA, 3*NF/4);
    // edge geometry + CSR build
    edge_geom_kernel<<<(EDG + TPB-1)/TPB, TPB>>>(xyz, nbr, unit, rbf, env, ei, ej);
    zeroi_kernel<<<(NN + TPB-1)/TPB, TPB>>>(deg, pos, NN);
    hist_kernel<<<(EDG + TPB-1)/TPB, TPB>>>(ei, deg);
    scan_kernel<<<1, 1024>>>(deg, startp);
    scatter_kernel<<<(EDG + TPB-1)/TPB, TPB>>>(ei, startp, pos, sortedp);

    const int RT = (NN + 127) / 128;   // 157 row tiles
    float* v_cur = vA; float* v_nxt = vB;

    for (int l = 0; l < NCONV; l++) {
        // phi = silu(s @ W1^T + b1) @ W2^T + b2
        mma_gemm_kernel<true ><<<dim3(1, RT, 1), TPB, GEMM_SMEM_BYTES>>>(
            s, 0, msg_W1 + (size_t)l*FEAT*FEAT, nullptr, msg_b1 + (size_t)l*FEAT,
            hid, nullptr, 0, NN, FEAT, FEAT);
        mma_gemm_kernel<false><<<dim3(3, RT, 1), TPB, GEMM_SMEM_BYTES>>>(
            hid, 0, msg_W2 + (size_t)l*384*FEAT, nullptr, msg_b2 + (size_t)l*384,
            phi, nullptr, 0, NN, 384, FEAT);
        // per-node gather/reduce: updates s in place, writes v_nxt = v_cur + dv
        edge_node_kernel<<<NN, 128>>>(phi, v_cur,
                                      dist_W + (size_t)l*384*NRBF, dist_b + (size_t)l*384,
                                      ej, unit, rbf, env, startp, sortedp,
                                      s, v_nxt);
        // u_v and v_v fused (shared A tile), batched over 3 spatial dims
        mma_gemm_kernel<false><<<dim3(2, RT, 3), TPB, GEMM_SMEM_BYTES>>>(
            v_nxt, (size_t)NF, upd_U + (size_t)l*FEAT*FEAT, upd_V + (size_t)l*FEAT*FEAT,
            nullptr, uv, vv, (size_t)NF, NN, FEAT, FEAT);
        // xcat = [s, ||v_v||]
        xcat_kernel<<<(NF + TPB-1)/TPB, TPB>>>(s, vv, xcat);
        // a = silu(xcat @ sW1^T + sb1) @ sW2^T + sb2
        mma_gemm_kernel<true ><<<dim3(1, RT, 1), TPB, GEMM_SMEM_BYTES>>>(
            xcat, 0, upd_sW1 + (size_t)l*FEAT*256, nullptr, upd_sb1 + (size_t)l*FEAT,
            hid, nullptr, 0, NN, FEAT, 256);
        mma_gemm_kernel<false><<<dim3(3, RT, 1), TPB, GEMM_SMEM_BYTES>>>(
            hid, 0, upd_sW2 + (size_t)l*384*FEAT, nullptr, upd_sb2 + (size_t)l*384,
            am, nullptr, 0, NN, 384, FEAT);
        // gated update (s and v_nxt in place)
        update_kernel<<<(NF + TPB-1)/TPB, TPB>>>(uv, vv, am, s, v_nxt);

        float* t = v_cur; v_cur = v_nxt; v_nxt = t;
    }

    output_kernel<<<(NF + TPB-1)/TPB, TPB>>>(s, v_cur, out);
}